// round 1
// baseline (speedup 1.0000x reference)
#include <cuda_runtime.h>
#include <math.h>

#define NN 100000
#define EE 1600000
#define DIN 384
#define HDIM 128
#define HHALF 64
#define NLAYERS 3
#define NRL 4
#define EPSBN 1e-5f

// ---------------- scratch (device globals; no allocation allowed) ------------
__device__ float g_h[NN * HDIM];    // current node features
__device__ float g_hw[NN * HDIM];   // h @ Wc[i]
__device__ float g_agg[NN * HDIM];  // aggregation buffer
__device__ float g_deg[NN];
__device__ float g_dinv[NN];

// ---------------- degree / normalization ------------------------------------
__global__ void deg_init_kernel() {
    int i = blockIdx.x * blockDim.x + threadIdx.x;
    if (i < NN) g_deg[i] = 1.0f;  // self-loop contribution
}

__global__ void deg_count_kernel(const int* __restrict__ ei) {
    int e = blockIdx.x * blockDim.x + threadIdx.x;
    if (e < EE) atomicAdd(&g_deg[ei[EE + e]], 1.0f);
}

__global__ void deg_fin_kernel() {
    int i = blockIdx.x * blockDim.x + threadIdx.x;
    if (i < NN) g_dinv[i] = rsqrtf(g_deg[i]);
}

// ---------------- generic fp32 tiled GEMM body -------------------------------
// C[M,128] = A[M,K] @ W[K,128] (+bias) (+relu).  BM=64, BN=128, BK=32.
// 256 threads, thread tile 4x8.
template <int K, bool RELU, bool BIAS>
__device__ __forceinline__ void gemm_body(const float* __restrict__ A,
                                          const float* __restrict__ W,
                                          const float* __restrict__ bias,
                                          float* __restrict__ C) {
    __shared__ float As[64][33];
    __shared__ float Ws[32][128];
    const int tid = threadIdx.x;
    const int tx = tid & 15;        // 16 col-groups of 8
    const int ty = tid >> 4;        // 16 row-groups of 4
    const int m0 = blockIdx.x * 64;

    float acc[4][8];
#pragma unroll
    for (int i = 0; i < 4; i++)
#pragma unroll
        for (int j = 0; j < 8; j++) acc[i][j] = 0.0f;

    for (int k0 = 0; k0 < K; k0 += 32) {
#pragma unroll
        for (int i = 0; i < 8; i++) {
            int idx = tid + i * 256;
            int r = idx >> 5, c = idx & 31;
            int gr = m0 + r;
            As[r][c] = (gr < NN) ? A[(size_t)gr * K + k0 + c] : 0.0f;
        }
#pragma unroll
        for (int i = 0; i < 16; i++) {
            int idx = tid + i * 256;
            int r = idx >> 7, c = idx & 127;
            Ws[r][c] = W[(size_t)(k0 + r) * 128 + c];
        }
        __syncthreads();
#pragma unroll
        for (int k = 0; k < 32; k++) {
            float a[4];
#pragma unroll
            for (int i = 0; i < 4; i++) a[i] = As[ty * 4 + i][k];
            float4 b0 = *(const float4*)&Ws[k][tx * 8];
            float4 b1 = *(const float4*)&Ws[k][tx * 8 + 4];
            float b[8] = {b0.x, b0.y, b0.z, b0.w, b1.x, b1.y, b1.z, b1.w};
#pragma unroll
            for (int i = 0; i < 4; i++)
#pragma unroll
                for (int j = 0; j < 8; j++) acc[i][j] = fmaf(a[i], b[j], acc[i][j]);
        }
        __syncthreads();
    }
#pragma unroll
    for (int i = 0; i < 4; i++) {
        int gr = m0 + ty * 4 + i;
        if (gr >= NN) continue;
        float* cp = C + (size_t)gr * 128 + tx * 8;
#pragma unroll
        for (int j = 0; j < 8; j++) {
            float v = acc[i][j];
            if (BIAS) v += bias[tx * 8 + j];
            if (RELU) v = fmaxf(v, 0.0f);
            cp[j] = v;
        }
    }
}

__global__ void gemm_pre_kernel(const float* __restrict__ x,
                                const float* __restrict__ Wp,
                                const float* __restrict__ bp) {
    gemm_body<DIN, true, true>(x, Wp, bp, g_h);
}

__global__ void gemm_layer_kernel(const float* __restrict__ Wc_i) {
    gemm_body<HDIM, false, false>(g_h, Wc_i, nullptr, g_hw);
}

// ---------------- aggregation ------------------------------------------------
// agg[n,j] = hw[n,j] * dinv[n]^2 + bc[j]
__global__ void init_agg_kernel(const float* __restrict__ bc_i) {
    int idx = blockIdx.x * blockDim.x + threadIdx.x;  // over NN*HDIM (= 12.8M, fits int)
    int n = idx >> 7;
    int j = idx & 127;
    float d = g_dinv[n];
    g_agg[idx] = g_hw[idx] * d * d + bc_i[j];
}

// one warp per edge: agg[dst] += hw[src] * dinv[src]*dinv[dst]
__global__ void scatter_kernel(const int* __restrict__ ei) {
    int gt = blockIdx.x * blockDim.x + threadIdx.x;
    int e = gt >> 5;
    int l = threadIdx.x & 31;
    if (e >= EE) return;
    int src = ei[e];
    int dst = ei[EE + e];
    float coef = g_dinv[src] * g_dinv[dst];
    float4 v = *(const float4*)(g_hw + (size_t)src * HDIM + l * 4);
    float* p = g_agg + (size_t)dst * HDIM + l * 4;
    asm volatile("red.global.add.v4.f32 [%0], {%1,%2,%3,%4};"
                 :: "l"(p), "f"(v.x * coef), "f"(v.y * coef),
                    "f"(v.z * coef), "f"(v.w * coef)
                 : "memory");
}

// h = relu(bn(agg)) (+ h if residual)
__global__ void bn_relu_res_kernel(const float* __restrict__ rmean,
                                   const float* __restrict__ rvar,
                                   const float* __restrict__ gamma,
                                   const float* __restrict__ beta,
                                   int residual) {
    int idx = blockIdx.x * blockDim.x + threadIdx.x;
    int j = idx & 127;
    float v = (g_agg[idx] - rmean[j]) * rsqrtf(rvar[j] + EPSBN) * gamma[j] + beta[j];
    v = fmaxf(v, 0.0f);
    g_h[idx] = residual ? (g_h[idx] + v) : v;
}

// ---------------- heads ------------------------------------------------------
// out layout: [0,N) risk_scores ; [N,5N) risk_logits row-major [N,4] ; [5N,6N) relevance
__global__ void heads_kernel(const float* __restrict__ rs_W1, const float* __restrict__ rs_b1,
                             const float* __restrict__ rs_W2, const float* __restrict__ rs_b2,
                             const float* __restrict__ rl_W1, const float* __restrict__ rl_b1,
                             const float* __restrict__ rl_W2, const float* __restrict__ rl_b2,
                             const float* __restrict__ rel_W1, const float* __restrict__ rel_b1,
                             const float* __restrict__ rel_W2, const float* __restrict__ rel_b2,
                             float* __restrict__ out) {
    __shared__ float hs[8][HDIM];
    __shared__ float w1s[HDIM * HHALF];
    __shared__ float w2s[HHALF * NRL];
    __shared__ float b1s[HHALF];
    __shared__ float b2s[NRL];

    const int tid = threadIdx.x;
    const int w = tid >> 5;
    const int l = tid & 31;
    const int nbase = blockIdx.x * 8;

#pragma unroll
    for (int i = 0; i < 4; i++) {
        int idx = tid + i * 256;
        int r = idx >> 7, c = idx & 127;
        int n = nbase + r;
        hs[r][c] = (n < NN) ? g_h[(size_t)n * HDIM + c] : 0.0f;
    }
    const int n = nbase + w;
    const bool valid = (n < NN);

    for (int head = 0; head < 3; head++) {
        const float *W1, *B1, *W2, *B2;
        int nout;
        if (head == 0)      { W1 = rs_W1;  B1 = rs_b1;  W2 = rs_W2;  B2 = rs_b2;  nout = 1; }
        else if (head == 1) { W1 = rl_W1;  B1 = rl_b1;  W2 = rl_W2;  B2 = rl_b2;  nout = NRL; }
        else                { W1 = rel_W1; B1 = rel_b1; W2 = rel_W2; B2 = rel_b2; nout = 1; }

        __syncthreads();
        for (int i = tid; i < HDIM * HHALF; i += 256) w1s[i] = W1[i];
        if (tid < HHALF) b1s[tid] = B1[tid];
        if (tid < HHALF * nout) w2s[tid] = W2[tid];
        if (tid < nout) b2s[tid] = B2[tid];
        __syncthreads();

        if (valid) {
            float a0 = b1s[l];
            float a1 = b1s[l + 32];
#pragma unroll 8
            for (int k = 0; k < HDIM; k++) {
                float hv = hs[w][k];
                a0 = fmaf(hv, w1s[k * HHALF + l], a0);
                a1 = fmaf(hv, w1s[k * HHALF + l + 32], a1);
            }
            a0 = fmaxf(a0, 0.0f);
            a1 = fmaxf(a1, 0.0f);
            if (nout == 1) {
                float p = a0 * w2s[l] + a1 * w2s[l + 32];
#pragma unroll
                for (int o = 16; o; o >>= 1) p += __shfl_xor_sync(0xffffffffu, p, o);
                if (l == 0) {
                    float v = p + b2s[0];
                    float sg = 1.0f / (1.0f + expf(-v));
                    if (head == 0) out[n] = sg;
                    else           out[(size_t)5 * NN + n] = sg;
                }
            } else {
                float p[NRL];
#pragma unroll
                for (int c = 0; c < NRL; c++)
                    p[c] = a0 * w2s[l * NRL + c] + a1 * w2s[(l + 32) * NRL + c];
#pragma unroll
                for (int c = 0; c < NRL; c++)
#pragma unroll
                    for (int o = 16; o; o >>= 1) p[c] += __shfl_xor_sync(0xffffffffu, p[c], o);
                if (l == 0) {
#pragma unroll
                    for (int c = 0; c < NRL; c++)
                        out[(size_t)NN + (size_t)n * NRL + c] = p[c] + b2s[c];
                }
            }
        }
    }
}

// ---------------- launch ------------------------------------------------------
extern "C" void kernel_launch(void* const* d_in, const int* in_sizes, int n_in,
                              void* d_out, int out_size) {
    const float* x      = (const float*)d_in[0];
    const int*   ei     = (const int*)  d_in[1];
    const float* Wp     = (const float*)d_in[2];
    const float* bp     = (const float*)d_in[3];
    const float* Wc     = (const float*)d_in[4];
    const float* bc     = (const float*)d_in[5];
    const float* gamma  = (const float*)d_in[6];
    const float* beta   = (const float*)d_in[7];
    const float* rmean  = (const float*)d_in[8];
    const float* rvar   = (const float*)d_in[9];
    const float* rel_W1 = (const float*)d_in[10];
    const float* rel_b1 = (const float*)d_in[11];
    const float* rel_W2 = (const float*)d_in[12];
    const float* rel_b2 = (const float*)d_in[13];
    const float* rs_W1  = (const float*)d_in[14];
    const float* rs_b1  = (const float*)d_in[15];
    const float* rs_W2  = (const float*)d_in[16];
    const float* rs_b2  = (const float*)d_in[17];
    const float* rl_W1  = (const float*)d_in[18];
    const float* rl_b1  = (const float*)d_in[19];
    const float* rl_W2  = (const float*)d_in[20];
    const float* rl_b2  = (const float*)d_in[21];
    float* out = (float*)d_out;

    const int T = 256;
    // degrees + symmetric norm
    deg_init_kernel<<<(NN + T - 1) / T, T>>>();
    deg_count_kernel<<<(EE + T - 1) / T, T>>>(ei);
    deg_fin_kernel<<<(NN + T - 1) / T, T>>>();

    // h = relu(x @ Wp + bp)
    gemm_pre_kernel<<<(NN + 63) / 64, T>>>(x, Wp, bp);

    const int elem_blocks = (NN * HDIM) / T;  // 50000 exactly
    for (int i = 0; i < NLAYERS; i++) {
        gemm_layer_kernel<<<(NN + 63) / 64, T>>>(Wc + (size_t)i * HDIM * HDIM);
        init_agg_kernel<<<elem_blocks, T>>>(bc + (size_t)i * HDIM);
        scatter_kernel<<<(EE * 32) / T, T>>>(ei);
        bn_relu_res_kernel<<<elem_blocks, T>>>(rmean + (size_t)i * HDIM,
                                               rvar + (size_t)i * HDIM,
                                               gamma + (size_t)i * HDIM,
                                               beta + (size_t)i * HDIM,
                                               i > 0 ? 1 : 0);
    }

    heads_kernel<<<(NN + 7) / 8, T>>>(rs_W1, rs_b1, rs_W2, rs_b2,
                                      rl_W1, rl_b1, rl_W2, rl_b2,
                                      rel_W1, rel_b1, rel_W2, rel_b2,
                                      out);
}

// round 2
// speedup vs baseline: 1.2725x; 1.2725x over previous
#include <cuda_runtime.h>
#include <math.h>

#define NN 100000
#define EE 1600000
#define DIN 384
#define HDIM 128
#define HHALF 64
#define NLAYERS 3
#define NRL 4
#define EPSBN 1e-5f

// ---------------- scratch (device globals; no allocation allowed) ------------
__device__ float g_h[NN * HDIM];    // current node features
__device__ float g_hw[NN * HDIM];   // (h @ Wc[i]) * dinv[row]
__device__ float g_deg[NN];
__device__ float g_dinv[NN];
__device__ int   g_cnt[NN];
__device__ int   g_rowptr[NN + 1];
__device__ int   g_csr_src[EE];

// ---------------- degree / normalization ------------------------------------
__global__ void deg_init_kernel() {
    int i = blockIdx.x * blockDim.x + threadIdx.x;
    if (i < NN) { g_deg[i] = 1.0f; g_cnt[i] = 0; }
}

__global__ void deg_count_kernel(const int* __restrict__ ei) {
    int e = blockIdx.x * blockDim.x + threadIdx.x;
    if (e < EE) {
        int d = ei[EE + e];
        atomicAdd(&g_deg[d], 1.0f);
        atomicAdd(&g_cnt[d], 1);
    }
}

__global__ void deg_fin_kernel() {
    int i = blockIdx.x * blockDim.x + threadIdx.x;
    if (i < NN) g_dinv[i] = rsqrtf(g_deg[i]);
}

// single-block scan over g_cnt -> g_rowptr (exclusive), also re-zero g_cnt
__global__ void scan_kernel() {
    __shared__ int ssum[1024];
    const int T = 1024;
    int tid = threadIdx.x;
    const int chunk = (NN + T - 1) / T;  // 98
    int start = tid * chunk;
    int end = start + chunk; if (end > NN) end = NN;
    int s = 0;
    for (int i = start; i < end; i++) s += g_cnt[i];
    ssum[tid] = s;
    __syncthreads();
    for (int o = 1; o < T; o <<= 1) {
        int v = (tid >= o) ? ssum[tid - o] : 0;
        __syncthreads();
        ssum[tid] += v;
        __syncthreads();
    }
    int base = (tid > 0) ? ssum[tid - 1] : 0;
    for (int i = start; i < end; i++) {
        int c = g_cnt[i];
        g_rowptr[i] = base;
        g_cnt[i] = 0;
        base += c;
    }
    if (tid == T - 1) g_rowptr[NN] = base;
}

__global__ void csr_fill_kernel(const int* __restrict__ ei) {
    int e = blockIdx.x * blockDim.x + threadIdx.x;
    if (e >= EE) return;
    int src = ei[e];
    int dst = ei[EE + e];
    int pos = g_rowptr[dst] + atomicAdd(&g_cnt[dst], 1);
    g_csr_src[pos] = src;
}

// ---------------- generic fp32 tiled GEMM body -------------------------------
// C[M,128] = A[M,K] @ W[K,128] (+bias) (+relu) (*dinv[row]).  BM=64, BN=128, BK=32.
template <int K, bool RELU, bool BIAS, bool SCALE>
__device__ __forceinline__ void gemm_body(const float* __restrict__ A,
                                          const float* __restrict__ W,
                                          const float* __restrict__ bias,
                                          float* __restrict__ C) {
    __shared__ float As[64][33];
    __shared__ float Ws[32][128];
    const int tid = threadIdx.x;
    const int tx = tid & 15;        // 16 col-groups of 8
    const int ty = tid >> 4;        // 16 row-groups of 4
    const int m0 = blockIdx.x * 64;

    float acc[4][8];
#pragma unroll
    for (int i = 0; i < 4; i++)
#pragma unroll
        for (int j = 0; j < 8; j++) acc[i][j] = 0.0f;

    for (int k0 = 0; k0 < K; k0 += 32) {
#pragma unroll
        for (int i = 0; i < 8; i++) {
            int idx = tid + i * 256;
            int r = idx >> 5, c = idx & 31;
            int gr = m0 + r;
            As[r][c] = (gr < NN) ? A[(size_t)gr * K + k0 + c] : 0.0f;
        }
#pragma unroll
        for (int i = 0; i < 16; i++) {
            int idx = tid + i * 256;
            int r = idx >> 7, c = idx & 127;
            Ws[r][c] = W[(size_t)(k0 + r) * 128 + c];
        }
        __syncthreads();
#pragma unroll
        for (int k = 0; k < 32; k++) {
            float a[4];
#pragma unroll
            for (int i = 0; i < 4; i++) a[i] = As[ty * 4 + i][k];
            float4 b0 = *(const float4*)&Ws[k][tx * 8];
            float4 b1 = *(const float4*)&Ws[k][tx * 8 + 4];
            float b[8] = {b0.x, b0.y, b0.z, b0.w, b1.x, b1.y, b1.z, b1.w};
#pragma unroll
            for (int i = 0; i < 4; i++)
#pragma unroll
                for (int j = 0; j < 8; j++) acc[i][j] = fmaf(a[i], b[j], acc[i][j]);
        }
        __syncthreads();
    }
#pragma unroll
    for (int i = 0; i < 4; i++) {
        int gr = m0 + ty * 4 + i;
        if (gr >= NN) continue;
        float scale = SCALE ? g_dinv[gr] : 1.0f;
        float* cp = C + (size_t)gr * 128 + tx * 8;
#pragma unroll
        for (int j = 0; j < 8; j++) {
            float v = acc[i][j];
            if (BIAS) v += bias[tx * 8 + j];
            if (RELU) v = fmaxf(v, 0.0f);
            if (SCALE) v *= scale;
            cp[j] = v;
        }
    }
}

__global__ void gemm_pre_kernel(const float* __restrict__ x,
                                const float* __restrict__ Wp,
                                const float* __restrict__ bp) {
    gemm_body<DIN, true, true, false>(x, Wp, bp, g_h);
}

__global__ void gemm_layer_kernel(const float* __restrict__ Wc_i) {
    gemm_body<HDIM, false, false, true>(g_h, Wc_i, nullptr, g_hw);
}

// ---------------- fused gather + self + bias + BN + relu + residual ----------
// one warp per node:
//   acc = hws[n] + sum_{src in CSR(n)} hws[src]      (hws already * dinv[src])
//   v   = acc * dinv[n] + bc
//   v   = BN(v); v = relu(v); h[n] = v (+ h_prev[n] if residual)
__global__ void gather_kernel(const float* __restrict__ bc_i,
                              const float* __restrict__ rmean,
                              const float* __restrict__ rvar,
                              const float* __restrict__ gamma,
                              const float* __restrict__ beta,
                              int residual) {
    int warp = (blockIdx.x * blockDim.x + threadIdx.x) >> 5;
    int l = threadIdx.x & 31;
    if (warp >= NN) return;
    const int n = warp;
    const int c0 = l * 4;

    const float4* hw4 = (const float4*)g_hw;
    float4 acc = hw4[(size_t)n * 32 + l];  // self term (pre-scaled by dinv[n])

    int j = g_rowptr[n];
    const int end = g_rowptr[n + 1];
    // unroll by 4 for MLP
    for (; j + 4 <= end; j += 4) {
        int s0 = __ldg(&g_csr_src[j + 0]);
        int s1 = __ldg(&g_csr_src[j + 1]);
        int s2 = __ldg(&g_csr_src[j + 2]);
        int s3 = __ldg(&g_csr_src[j + 3]);
        float4 v0 = hw4[(size_t)s0 * 32 + l];
        float4 v1 = hw4[(size_t)s1 * 32 + l];
        float4 v2 = hw4[(size_t)s2 * 32 + l];
        float4 v3 = hw4[(size_t)s3 * 32 + l];
        acc.x += v0.x + v1.x + v2.x + v3.x;
        acc.y += v0.y + v1.y + v2.y + v3.y;
        acc.z += v0.z + v1.z + v2.z + v3.z;
        acc.w += v0.w + v1.w + v2.w + v3.w;
    }
    for (; j < end; j++) {
        int s = __ldg(&g_csr_src[j]);
        float4 v = hw4[(size_t)s * 32 + l];
        acc.x += v.x; acc.y += v.y; acc.z += v.z; acc.w += v.w;
    }

    const float dn = g_dinv[n];
    float4 bc4 = *(const float4*)(bc_i + c0);
    float4 rm4 = *(const float4*)(rmean + c0);
    float4 rv4 = *(const float4*)(rvar + c0);
    float4 ga4 = *(const float4*)(gamma + c0);
    float4 be4 = *(const float4*)(beta + c0);

    float4 o;
    o.x = fmaxf((acc.x * dn + bc4.x - rm4.x) * rsqrtf(rv4.x + EPSBN) * ga4.x + be4.x, 0.0f);
    o.y = fmaxf((acc.y * dn + bc4.y - rm4.y) * rsqrtf(rv4.y + EPSBN) * ga4.y + be4.y, 0.0f);
    o.z = fmaxf((acc.z * dn + bc4.z - rm4.z) * rsqrtf(rv4.z + EPSBN) * ga4.z + be4.z, 0.0f);
    o.w = fmaxf((acc.w * dn + bc4.w - rm4.w) * rsqrtf(rv4.w + EPSBN) * ga4.w + be4.w, 0.0f);

    float4* h4 = (float4*)g_h;
    if (residual) {
        float4 hp = h4[(size_t)n * 32 + l];
        o.x += hp.x; o.y += hp.y; o.z += hp.z; o.w += hp.w;
    }
    h4[(size_t)n * 32 + l] = o;
}

// ---------------- heads ------------------------------------------------------
// out layout: [0,N) risk_scores ; [N,5N) risk_logits row-major [N,4] ; [5N,6N) relevance
__global__ void heads_kernel(const float* __restrict__ rs_W1, const float* __restrict__ rs_b1,
                             const float* __restrict__ rs_W2, const float* __restrict__ rs_b2,
                             const float* __restrict__ rl_W1, const float* __restrict__ rl_b1,
                             const float* __restrict__ rl_W2, const float* __restrict__ rl_b2,
                             const float* __restrict__ rel_W1, const float* __restrict__ rel_b1,
                             const float* __restrict__ rel_W2, const float* __restrict__ rel_b2,
                             float* __restrict__ out) {
    __shared__ float hs[8][HDIM];
    __shared__ float w1s[HDIM * HHALF];
    __shared__ float w2s[HHALF * NRL];
    __shared__ float b1s[HHALF];
    __shared__ float b2s[NRL];

    const int tid = threadIdx.x;
    const int w = tid >> 5;
    const int l = tid & 31;
    const int nbase = blockIdx.x * 8;

#pragma unroll
    for (int i = 0; i < 4; i++) {
        int idx = tid + i * 256;
        int r = idx >> 7, c = idx & 127;
        int n = nbase + r;
        hs[r][c] = (n < NN) ? g_h[(size_t)n * HDIM + c] : 0.0f;
    }
    const int n = nbase + w;
    const bool valid = (n < NN);

    for (int head = 0; head < 3; head++) {
        const float *W1, *B1, *W2, *B2;
        int nout;
        if (head == 0)      { W1 = rs_W1;  B1 = rs_b1;  W2 = rs_W2;  B2 = rs_b2;  nout = 1; }
        else if (head == 1) { W1 = rl_W1;  B1 = rl_b1;  W2 = rl_W2;  B2 = rl_b2;  nout = NRL; }
        else                { W1 = rel_W1; B1 = rel_b1; W2 = rel_W2; B2 = rel_b2; nout = 1; }

        __syncthreads();
        for (int i = tid; i < HDIM * HHALF; i += 256) w1s[i] = W1[i];
        if (tid < HHALF) b1s[tid] = B1[tid];
        if (tid < HHALF * nout) w2s[tid] = W2[tid];
        if (tid < nout) b2s[tid] = B2[tid];
        __syncthreads();

        if (valid) {
            float a0 = b1s[l];
            float a1 = b1s[l + 32];
#pragma unroll 8
            for (int k = 0; k < HDIM; k++) {
                float hv = hs[w][k];
                a0 = fmaf(hv, w1s[k * HHALF + l], a0);
                a1 = fmaf(hv, w1s[k * HHALF + l + 32], a1);
            }
            a0 = fmaxf(a0, 0.0f);
            a1 = fmaxf(a1, 0.0f);
            if (nout == 1) {
                float p = a0 * w2s[l] + a1 * w2s[l + 32];
#pragma unroll
                for (int o = 16; o; o >>= 1) p += __shfl_xor_sync(0xffffffffu, p, o);
                if (l == 0) {
                    float v = p + b2s[0];
                    float sg = 1.0f / (1.0f + expf(-v));
                    if (head == 0) out[n] = sg;
                    else           out[(size_t)5 * NN + n] = sg;
                }
            } else {
                float p[NRL];
#pragma unroll
                for (int c = 0; c < NRL; c++)
                    p[c] = a0 * w2s[l * NRL + c] + a1 * w2s[(l + 32) * NRL + c];
#pragma unroll
                for (int c = 0; c < NRL; c++)
#pragma unroll
                    for (int o = 16; o; o >>= 1) p[c] += __shfl_xor_sync(0xffffffffu, p[c], o);
                if (l == 0) {
#pragma unroll
                    for (int c = 0; c < NRL; c++)
                        out[(size_t)NN + (size_t)n * NRL + c] = p[c] + b2s[c];
                }
            }
        }
    }
}

// ---------------- launch ------------------------------------------------------
extern "C" void kernel_launch(void* const* d_in, const int* in_sizes, int n_in,
                              void* d_out, int out_size) {
    const float* x      = (const float*)d_in[0];
    const int*   ei     = (const int*)  d_in[1];
    const float* Wp     = (const float*)d_in[2];
    const float* bp     = (const float*)d_in[3];
    const float* Wc     = (const float*)d_in[4];
    const float* bc     = (const float*)d_in[5];
    const float* gamma  = (const float*)d_in[6];
    const float* beta   = (const float*)d_in[7];
    const float* rmean  = (const float*)d_in[8];
    const float* rvar   = (const float*)d_in[9];
    const float* rel_W1 = (const float*)d_in[10];
    const float* rel_b1 = (const float*)d_in[11];
    const float* rel_W2 = (const float*)d_in[12];
    const float* rel_b2 = (const float*)d_in[13];
    const float* rs_W1  = (const float*)d_in[14];
    const float* rs_b1  = (const float*)d_in[15];
    const float* rs_W2  = (const float*)d_in[16];
    const float* rs_b2  = (const float*)d_in[17];
    const float* rl_W1  = (const float*)d_in[18];
    const float* rl_b1  = (const float*)d_in[19];
    const float* rl_W2  = (const float*)d_in[20];
    const float* rl_b2  = (const float*)d_in[21];
    float* out = (float*)d_out;

    const int T = 256;
    // degrees + CSR build
    deg_init_kernel<<<(NN + T - 1) / T, T>>>();
    deg_count_kernel<<<(EE + T - 1) / T, T>>>(ei);
    deg_fin_kernel<<<(NN + T - 1) / T, T>>>();
    scan_kernel<<<1, 1024>>>();
    csr_fill_kernel<<<(EE + T - 1) / T, T>>>(ei);

    // h = relu(x @ Wp + bp)  (overlaps with CSR build on same stream order; fine)
    gemm_pre_kernel<<<(NN + 63) / 64, T>>>(x, Wp, bp);

    const int gather_blocks = (NN * 32 + T - 1) / T;  // 12500
    for (int i = 0; i < NLAYERS; i++) {
        gemm_layer_kernel<<<(NN + 63) / 64, T>>>(Wc + (size_t)i * HDIM * HDIM);
        gather_kernel<<<gather_blocks, T>>>(bc + (size_t)i * HDIM,
                                            rmean + (size_t)i * HDIM,
                                            rvar + (size_t)i * HDIM,
                                            gamma + (size_t)i * HDIM,
                                            beta + (size_t)i * HDIM,
                                            i > 0 ? 1 : 0);
    }

    heads_kernel<<<(NN + 7) / 8, T>>>(rs_W1, rs_b1, rs_W2, rs_b2,
                                      rl_W1, rl_b1, rl_W2, rl_b2,
                                      rel_W1, rel_b1, rel_W2, rel_b2,
                                      out);
}

// round 3
// speedup vs baseline: 1.5360x; 1.2071x over previous
#include <cuda_runtime.h>
#include <math.h>

#define NN 100000
#define EE 1600000
#define DIN 384
#define HDIM 128
#define HHALF 64
#define NLAYERS 3
#define NRL 4
#define EPSBN 1e-5f

#define SCAN_NB 200
#define SCAN_CHUNK 500

// ---------------- scratch (device globals; no allocation allowed) ------------
__device__ float g_h[NN * HDIM];    // current node features
__device__ float g_hw[NN * HDIM];   // (h @ Wc[i]) * dinv[row]
__device__ float g_dinv[NN];
__device__ int   g_cnt[NN];
__device__ int   g_rowptr[NN + 1];
__device__ int   g_csr_src[EE];
__device__ int   g_bsum[SCAN_NB];
__device__ int   g_boff[SCAN_NB];

// ---------------- degree count ------------------------------------------------
__global__ void deg_init_kernel() {
    int i = blockIdx.x * blockDim.x + threadIdx.x;
    if (i < NN) g_cnt[i] = 0;
}

__global__ void deg_count_kernel(const int* __restrict__ ei) {
    int e = blockIdx.x * blockDim.x + threadIdx.x;
    if (e < EE) atomicAdd(&g_cnt[ei[EE + e]], 1);
}

// ---------------- 3-phase parallel scan --------------------------------------
__global__ void scan_partial_kernel() {   // grid SCAN_NB, block 512
    __shared__ int sh[512];
    int b = blockIdx.x, t = threadIdx.x;
    int i = b * SCAN_CHUNK + t;
    sh[t] = (t < SCAN_CHUNK) ? g_cnt[i] : 0;
    __syncthreads();
#pragma unroll
    for (int o = 256; o; o >>= 1) {
        if (t < o) sh[t] += sh[t + o];
        __syncthreads();
    }
    if (t == 0) g_bsum[b] = sh[0];
}

__global__ void scan_bsum_kernel() {      // 1 block, 256 threads
    __shared__ int sh[256];
    int t = threadIdx.x;
    sh[t] = (t < SCAN_NB) ? g_bsum[t] : 0;
    __syncthreads();
#pragma unroll
    for (int o = 1; o < 256; o <<= 1) {
        int v = (t >= o) ? sh[t - o] : 0;
        __syncthreads();
        sh[t] += v;
        __syncthreads();
    }
    if (t < SCAN_NB) g_boff[t] = (t ? sh[t - 1] : 0);
    if (t == 0) g_rowptr[NN] = EE;
}

__global__ void scan_fill_kernel() {      // grid SCAN_NB, block 512; also dinv + re-zero cnt
    __shared__ int sh[512];
    int b = blockIdx.x, t = threadIdx.x;
    int i = b * SCAN_CHUNK + t;
    int c = (t < SCAN_CHUNK) ? g_cnt[i] : 0;
    sh[t] = c;
    __syncthreads();
#pragma unroll
    for (int o = 1; o < 512; o <<= 1) {
        int v = (t >= o) ? sh[t - o] : 0;
        __syncthreads();
        sh[t] += v;
        __syncthreads();
    }
    if (t < SCAN_CHUNK) {
        g_rowptr[i] = g_boff[b] + sh[t] - c;    // exclusive
        g_cnt[i] = 0;
        g_dinv[i] = rsqrtf((float)(c + 1));     // deg = in-degree + self loop
    }
}

__global__ void csr_fill_kernel(const int* __restrict__ ei) {
    int e = blockIdx.x * blockDim.x + threadIdx.x;
    if (e >= EE) return;
    int src = ei[e];
    int dst = ei[EE + e];
    int pos = g_rowptr[dst] + atomicAdd(&g_cnt[dst], 1);
    g_csr_src[pos] = src;
}

// ---------------- tf32 tensor-core GEMM --------------------------------------
__device__ __forceinline__ unsigned f2tf32(float x) {
    unsigned r;
    asm("cvt.rna.tf32.f32 %0, %1;" : "=r"(r) : "f"(x));
    return r;
}

__device__ __forceinline__ void mma_tf32(float* c, const unsigned* a, const unsigned* b) {
    asm volatile(
        "mma.sync.aligned.m16n8k8.row.col.f32.tf32.tf32.f32 "
        "{%0,%1,%2,%3}, {%4,%5,%6,%7}, {%8,%9}, {%0,%1,%2,%3};"
        : "+f"(c[0]), "+f"(c[1]), "+f"(c[2]), "+f"(c[3])
        : "r"(a[0]), "r"(a[1]), "r"(a[2]), "r"(a[3]), "r"(b[0]), "r"(b[1]));
}

// C[M,128] = A[M,K] @ W[K,128] (+bias)(+relu)(*dinv[row])
// BM=128, BN=128, BK=16. 256 threads, 8 warps as (wm 0..3) x (wn 0..1).
// Warp tile 32x64: 2 m16 tiles x 8 n8 tiles.
#define ASTRIDE 20
#define BSTRIDE 136
template <int K, bool RELU, bool BIAS, bool SCALE>
__device__ __forceinline__ void gemm_tf32_body(const float* __restrict__ A,
                                               const float* __restrict__ W,
                                               const float* __restrict__ bias,
                                               float* __restrict__ C) {
    __shared__ unsigned As[128 * ASTRIDE];
    __shared__ unsigned Bs[16 * BSTRIDE];
    const int tid = threadIdx.x;
    const int wid = tid >> 5, lane = tid & 31;
    const int wm = wid & 3, wn = wid >> 2;
    const int g = lane >> 2, t = lane & 3;
    const int m0 = blockIdx.x * 128;

    float acc[2][8][4];
#pragma unroll
    for (int mt = 0; mt < 2; mt++)
#pragma unroll
        for (int nt = 0; nt < 8; nt++)
#pragma unroll
            for (int i = 0; i < 4; i++) acc[mt][nt][i] = 0.0f;

    for (int k0 = 0; k0 < K; k0 += 16) {
        // A tile: 128 rows x 16 cols = 512 float4 slots
#pragma unroll
        for (int i = 0; i < 2; i++) {
            int s = tid + i * 256;
            int r = s >> 2, c4 = (s & 3) * 4;
            int gr = m0 + r;
            float4 v = (gr < NN) ? *(const float4*)(A + (size_t)gr * K + k0 + c4)
                                 : make_float4(0.f, 0.f, 0.f, 0.f);
            unsigned* p = &As[r * ASTRIDE + c4];
            p[0] = f2tf32(v.x); p[1] = f2tf32(v.y); p[2] = f2tf32(v.z); p[3] = f2tf32(v.w);
        }
        // B tile: 16 rows x 128 cols = 512 float4 slots
#pragma unroll
        for (int i = 0; i < 2; i++) {
            int s = tid + i * 256;
            int kr = s >> 5, c4 = (s & 31) * 4;
            float4 v = *(const float4*)(W + (size_t)(k0 + kr) * 128 + c4);
            unsigned* p = &Bs[kr * BSTRIDE + c4];
            p[0] = f2tf32(v.x); p[1] = f2tf32(v.y); p[2] = f2tf32(v.z); p[3] = f2tf32(v.w);
        }
        __syncthreads();

#pragma unroll
        for (int ks = 0; ks < 2; ks++) {
            unsigned a[2][4], bf[8][2];
#pragma unroll
            for (int mt = 0; mt < 2; mt++) {
                int r = wm * 32 + mt * 16 + g;
                int c = ks * 8 + t;
                a[mt][0] = As[r * ASTRIDE + c];
                a[mt][1] = As[(r + 8) * ASTRIDE + c];
                a[mt][2] = As[r * ASTRIDE + c + 4];
                a[mt][3] = As[(r + 8) * ASTRIDE + c + 4];
            }
#pragma unroll
            for (int nt = 0; nt < 8; nt++) {
                int n = wn * 64 + nt * 8 + g;
                int k = ks * 8 + t;
                bf[nt][0] = Bs[k * BSTRIDE + n];
                bf[nt][1] = Bs[(k + 4) * BSTRIDE + n];
            }
#pragma unroll
            for (int mt = 0; mt < 2; mt++)
#pragma unroll
                for (int nt = 0; nt < 8; nt++) mma_tf32(acc[mt][nt], a[mt], bf[nt]);
        }
        __syncthreads();
    }

    // epilogue
#pragma unroll
    for (int mt = 0; mt < 2; mt++) {
        int rbase = m0 + wm * 32 + mt * 16 + g;
#pragma unroll
        for (int half = 0; half < 2; half++) {
            int r = rbase + half * 8;
            if (r >= NN) continue;
            float s = SCALE ? g_dinv[r] : 1.0f;
#pragma unroll
            for (int nt = 0; nt < 8; nt++) {
                int col = wn * 64 + nt * 8 + 2 * t;
                float v0 = acc[mt][nt][half * 2 + 0];
                float v1 = acc[mt][nt][half * 2 + 1];
                if (BIAS) { v0 += bias[col]; v1 += bias[col + 1]; }
                if (RELU) { v0 = fmaxf(v0, 0.0f); v1 = fmaxf(v1, 0.0f); }
                if (SCALE) { v0 *= s; v1 *= s; }
                *(float2*)(C + (size_t)r * 128 + col) = make_float2(v0, v1);
            }
        }
    }
}

__global__ __launch_bounds__(256) void gemm_pre_kernel(const float* __restrict__ x,
                                                       const float* __restrict__ Wp,
                                                       const float* __restrict__ bp) {
    gemm_tf32_body<DIN, true, true, false>(x, Wp, bp, g_h);
}

__global__ __launch_bounds__(256) void gemm_layer_kernel(const float* __restrict__ Wc_i) {
    gemm_tf32_body<HDIM, false, false, true>(g_h, Wc_i, nullptr, g_hw);
}

// ---------------- fused gather + self + bias + BN + relu + residual ----------
__global__ void gather_kernel(const float* __restrict__ bc_i,
                              const float* __restrict__ rmean,
                              const float* __restrict__ rvar,
                              const float* __restrict__ gamma,
                              const float* __restrict__ beta,
                              int residual) {
    int warp = (blockIdx.x * blockDim.x + threadIdx.x) >> 5;
    int l = threadIdx.x & 31;
    if (warp >= NN) return;
    const int n = warp;
    const int c0 = l * 4;

    const float4* hw4 = (const float4*)g_hw;
    float4 acc0 = hw4[(size_t)n * 32 + l];  // self term (pre-scaled by dinv[n])
    float4 acc1 = make_float4(0.f, 0.f, 0.f, 0.f);

    int j = g_rowptr[n];
    const int end = g_rowptr[n + 1];
    for (; j + 8 <= end; j += 8) {
        int s0 = __ldg(&g_csr_src[j + 0]);
        int s1 = __ldg(&g_csr_src[j + 1]);
        int s2 = __ldg(&g_csr_src[j + 2]);
        int s3 = __ldg(&g_csr_src[j + 3]);
        int s4 = __ldg(&g_csr_src[j + 4]);
        int s5 = __ldg(&g_csr_src[j + 5]);
        int s6 = __ldg(&g_csr_src[j + 6]);
        int s7 = __ldg(&g_csr_src[j + 7]);
        float4 v0 = hw4[(size_t)s0 * 32 + l];
        float4 v1 = hw4[(size_t)s1 * 32 + l];
        float4 v2 = hw4[(size_t)s2 * 32 + l];
        float4 v3 = hw4[(size_t)s3 * 32 + l];
        float4 v4 = hw4[(size_t)s4 * 32 + l];
        float4 v5 = hw4[(size_t)s5 * 32 + l];
        float4 v6 = hw4[(size_t)s6 * 32 + l];
        float4 v7 = hw4[(size_t)s7 * 32 + l];
        acc0.x += v0.x + v1.x + v2.x + v3.x;
        acc0.y += v0.y + v1.y + v2.y + v3.y;
        acc0.z += v0.z + v1.z + v2.z + v3.z;
        acc0.w += v0.w + v1.w + v2.w + v3.w;
        acc1.x += v4.x + v5.x + v6.x + v7.x;
        acc1.y += v4.y + v5.y + v6.y + v7.y;
        acc1.z += v4.z + v5.z + v6.z + v7.z;
        acc1.w += v4.w + v5.w + v6.w + v7.w;
    }
    for (; j < end; j++) {
        int s = __ldg(&g_csr_src[j]);
        float4 v = hw4[(size_t)s * 32 + l];
        acc1.x += v.x; acc1.y += v.y; acc1.z += v.z; acc1.w += v.w;
    }
    float4 acc = make_float4(acc0.x + acc1.x, acc0.y + acc1.y,
                             acc0.z + acc1.z, acc0.w + acc1.w);

    const float dn = g_dinv[n];
    float4 bc4 = *(const float4*)(bc_i + c0);
    float4 rm4 = *(const float4*)(rmean + c0);
    float4 rv4 = *(const float4*)(rvar + c0);
    float4 ga4 = *(const float4*)(gamma + c0);
    float4 be4 = *(const float4*)(beta + c0);

    float4 o;
    o.x = fmaxf((acc.x * dn + bc4.x - rm4.x) * rsqrtf(rv4.x + EPSBN) * ga4.x + be4.x, 0.0f);
    o.y = fmaxf((acc.y * dn + bc4.y - rm4.y) * rsqrtf(rv4.y + EPSBN) * ga4.y + be4.y, 0.0f);
    o.z = fmaxf((acc.z * dn + bc4.z - rm4.z) * rsqrtf(rv4.z + EPSBN) * ga4.z + be4.z, 0.0f);
    o.w = fmaxf((acc.w * dn + bc4.w - rm4.w) * rsqrtf(rv4.w + EPSBN) * ga4.w + be4.w, 0.0f);

    float4* h4 = (float4*)g_h;
    if (residual) {
        float4 hp = h4[(size_t)n * 32 + l];
        o.x += hp.x; o.y += hp.y; o.z += hp.z; o.w += hp.w;
    }
    h4[(size_t)n * 32 + l] = o;
}

// ---------------- heads ------------------------------------------------------
// out layout: [0,N) risk_scores ; [N,5N) risk_logits row-major [N,4] ; [5N,6N) relevance
__global__ void heads_kernel(const float* __restrict__ rs_W1, const float* __restrict__ rs_b1,
                             const float* __restrict__ rs_W2, const float* __restrict__ rs_b2,
                             const float* __restrict__ rl_W1, const float* __restrict__ rl_b1,
                             const float* __restrict__ rl_W2, const float* __restrict__ rl_b2,
                             const float* __restrict__ rel_W1, const float* __restrict__ rel_b1,
                             const float* __restrict__ rel_W2, const float* __restrict__ rel_b2,
                             float* __restrict__ out) {
    __shared__ float hs[8][HDIM];
    __shared__ float w1s[HDIM * HHALF];
    __shared__ float w2s[HHALF * NRL];
    __shared__ float b1s[HHALF];
    __shared__ float b2s[NRL];

    const int tid = threadIdx.x;
    const int w = tid >> 5;
    const int l = tid & 31;
    const int nbase = blockIdx.x * 8;

#pragma unroll
    for (int i = 0; i < 4; i++) {
        int idx = tid + i * 256;
        int r = idx >> 7, c = idx & 127;
        int n = nbase + r;
        hs[r][c] = (n < NN) ? g_h[(size_t)n * HDIM + c] : 0.0f;
    }
    const int n = nbase + w;
    const bool valid = (n < NN);

    for (int head = 0; head < 3; head++) {
        const float *W1, *B1, *W2, *B2;
        int nout;
        if (head == 0)      { W1 = rs_W1;  B1 = rs_b1;  W2 = rs_W2;  B2 = rs_b2;  nout = 1; }
        else if (head == 1) { W1 = rl_W1;  B1 = rl_b1;  W2 = rl_W2;  B2 = rl_b2;  nout = NRL; }
        else                { W1 = rel_W1; B1 = rel_b1; W2 = rel_W2; B2 = rel_b2; nout = 1; }

        __syncthreads();
        for (int i = tid; i < HDIM * HHALF; i += 256) w1s[i] = W1[i];
        if (tid < HHALF) b1s[tid] = B1[tid];
        if (tid < HHALF * nout) w2s[tid] = W2[tid];
        if (tid < nout) b2s[tid] = B2[tid];
        __syncthreads();

        if (valid) {
            float a0 = b1s[l];
            float a1 = b1s[l + 32];
#pragma unroll 8
            for (int k = 0; k < HDIM; k++) {
                float hv = hs[w][k];
                a0 = fmaf(hv, w1s[k * HHALF + l], a0);
                a1 = fmaf(hv, w1s[k * HHALF + l + 32], a1);
            }
            a0 = fmaxf(a0, 0.0f);
            a1 = fmaxf(a1, 0.0f);
            if (nout == 1) {
                float p = a0 * w2s[l] + a1 * w2s[l + 32];
#pragma unroll
                for (int o = 16; o; o >>= 1) p += __shfl_xor_sync(0xffffffffu, p, o);
                if (l == 0) {
                    float v = p + b2s[0];
                    float sg = 1.0f / (1.0f + expf(-v));
                    if (head == 0) out[n] = sg;
                    else           out[(size_t)5 * NN + n] = sg;
                }
            } else {
                float p[NRL];
#pragma unroll
                for (int c = 0; c < NRL; c++)
                    p[c] = a0 * w2s[l * NRL + c] + a1 * w2s[(l + 32) * NRL + c];
#pragma unroll
                for (int c = 0; c < NRL; c++)
#pragma unroll
                    for (int o = 16; o; o >>= 1) p[c] += __shfl_xor_sync(0xffffffffu, p[c], o);
                if (l == 0) {
#pragma unroll
                    for (int c = 0; c < NRL; c++)
                        out[(size_t)NN + (size_t)n * NRL + c] = p[c] + b2s[c];
                }
            }
        }
    }
}

// ---------------- launch ------------------------------------------------------
extern "C" void kernel_launch(void* const* d_in, const int* in_sizes, int n_in,
                              void* d_out, int out_size) {
    const float* x      = (const float*)d_in[0];
    const int*   ei     = (const int*)  d_in[1];
    const float* Wp     = (const float*)d_in[2];
    const float* bp     = (const float*)d_in[3];
    const float* Wc     = (const float*)d_in[4];
    const float* bc     = (const float*)d_in[5];
    const float* gamma  = (const float*)d_in[6];
    const float* beta   = (const float*)d_in[7];
    const float* rmean  = (const float*)d_in[8];
    const float* rvar   = (const float*)d_in[9];
    const float* rel_W1 = (const float*)d_in[10];
    const float* rel_b1 = (const float*)d_in[11];
    const float* rel_W2 = (const float*)d_in[12];
    const float* rel_b2 = (const float*)d_in[13];
    const float* rs_W1  = (const float*)d_in[14];
    const float* rs_b1  = (const float*)d_in[15];
    const float* rs_W2  = (const float*)d_in[16];
    const float* rs_b2  = (const float*)d_in[17];
    const float* rl_W1  = (const float*)d_in[18];
    const float* rl_b1  = (const float*)d_in[19];
    const float* rl_W2  = (const float*)d_in[20];
    const float* rl_b2  = (const float*)d_in[21];
    float* out = (float*)d_out;

    const int T = 256;
    // degrees + CSR build
    deg_init_kernel<<<(NN + T - 1) / T, T>>>();
    deg_count_kernel<<<(EE + T - 1) / T, T>>>(ei);
    scan_partial_kernel<<<SCAN_NB, 512>>>();
    scan_bsum_kernel<<<1, 256>>>();
    scan_fill_kernel<<<SCAN_NB, 512>>>();
    csr_fill_kernel<<<(EE + T - 1) / T, T>>>(ei);

    const int gemm_blocks = (NN + 127) / 128;  // 782
    gemm_pre_kernel<<<gemm_blocks, 256>>>(x, Wp, bp);

    const int gather_blocks = (NN * 32 + T - 1) / T;  // 12500
    for (int i = 0; i < NLAYERS; i++) {
        gemm_layer_kernel<<<gemm_blocks, 256>>>(Wc + (size_t)i * HDIM * HDIM);
        gather_kernel<<<gather_blocks, T>>>(bc + (size_t)i * HDIM,
                                            rmean + (size_t)i * HDIM,
                                            rvar + (size_t)i * HDIM,
                                            gamma + (size_t)i * HDIM,
                                            beta + (size_t)i * HDIM,
                                            i > 0 ? 1 : 0);
    }

    heads_kernel<<<(NN + 7) / 8, T>>>(rs_W1, rs_b1, rs_W2, rs_b2,
                                      rl_W1, rl_b1, rl_W2, rl_b2,
                                      rel_W1, rel_b1, rel_W2, rel_b2,
                                      out);
}

// round 6
// speedup vs baseline: 4.0973x; 2.6675x over previous
#include <cuda_runtime.h>
#include <math.h>

#define NN 100000
#define EE 1600000
#define DIN 384
#define HDIM 128
#define HHALF 64
#define NLAYERS 3
#define NRL 4
#define EPSBN 1e-5f

#define SCAN_NB 200
#define SCAN_CHUNK 500

#define MIDC 192   // concatenated heads hidden width

// ---------------- scratch (device globals; no allocation allowed) ------------
__device__ float g_h[NN * HDIM];     // current node features
__device__ float g_hw[NN * HDIM];    // (h @ Wc[i]) * dinv[row]
__device__ float g_mid[NN * MIDC];   // heads hidden
__device__ float g_w1cat[HDIM * MIDC];
__device__ float g_b1cat[MIDC];
__device__ float g_dinv[NN];
__device__ int   g_cnt[NN];
__device__ int   g_rowptr[NN + 1];
__device__ int   g_csr_src[EE];
__device__ int   g_bsum[SCAN_NB];
__device__ int   g_boff[SCAN_NB];

// ---------------- heads weight concat ----------------------------------------
__global__ void w1cat_kernel(const float* __restrict__ rs_W1, const float* __restrict__ rs_b1,
                             const float* __restrict__ rl_W1, const float* __restrict__ rl_b1,
                             const float* __restrict__ rel_W1, const float* __restrict__ rel_b1) {
    int idx = blockIdx.x * blockDim.x + threadIdx.x;   // [0, 128*192)
    if (idx >= HDIM * MIDC) return;
    int k = idx / MIDC, c = idx % MIDC;
    int head = c >> 6, j = c & 63;
    const float* W1 = (head == 0) ? rs_W1 : (head == 1) ? rl_W1 : rel_W1;
    g_w1cat[idx] = W1[k * HHALF + j];
    if (k == 0) {
        const float* B1 = (head == 0) ? rs_b1 : (head == 1) ? rl_b1 : rel_b1;
        g_b1cat[c] = B1[j];
    }
}

// ---------------- degree count ------------------------------------------------
__global__ void deg_init_kernel() {
    int i = blockIdx.x * blockDim.x + threadIdx.x;
    if (i < NN) g_cnt[i] = 0;
}

__global__ void deg_count_kernel(const int* __restrict__ ei) {
    int e = blockIdx.x * blockDim.x + threadIdx.x;
    if (e < EE) atomicAdd(&g_cnt[ei[EE + e]], 1);
}

// ---------------- 3-phase parallel scan --------------------------------------
__global__ void scan_partial_kernel() {   // grid SCAN_NB, block 512
    __shared__ int sh[512];
    int b = blockIdx.x, t = threadIdx.x;
    int i = b * SCAN_CHUNK + t;
    sh[t] = (t < SCAN_CHUNK) ? g_cnt[i] : 0;
    __syncthreads();
#pragma unroll
    for (int o = 256; o; o >>= 1) {
        if (t < o) sh[t] += sh[t + o];
        __syncthreads();
    }
    if (t == 0) g_bsum[b] = sh[0];
}

__global__ void scan_bsum_kernel() {      // 1 block, 256 threads
    __shared__ int sh[256];
    int t = threadIdx.x;
    sh[t] = (t < SCAN_NB) ? g_bsum[t] : 0;
    __syncthreads();
#pragma unroll
    for (int o = 1; o < 256; o <<= 1) {
        int v = (t >= o) ? sh[t - o] : 0;
        __syncthreads();
        sh[t] += v;
        __syncthreads();
    }
    if (t < SCAN_NB) g_boff[t] = (t ? sh[t - 1] : 0);
    if (t == 0) g_rowptr[NN] = EE;
}

__global__ void scan_fill_kernel() {      // grid SCAN_NB, block 512
    __shared__ int sh[512];
    int b = blockIdx.x, t = threadIdx.x;
    int i = b * SCAN_CHUNK + t;
    int c = (t < SCAN_CHUNK) ? g_cnt[i] : 0;
    sh[t] = c;
    __syncthreads();
#pragma unroll
    for (int o = 1; o < 512; o <<= 1) {
        int v = (t >= o) ? sh[t - o] : 0;
        __syncthreads();
        sh[t] += v;
        __syncthreads();
    }
    if (t < SCAN_CHUNK) {
        g_rowptr[i] = g_boff[b] + sh[t] - c;    // exclusive
        g_cnt[i] = 0;
        g_dinv[i] = rsqrtf((float)(c + 1));     // deg = in-degree + self loop
    }
}

__global__ void csr_fill_kernel(const int* __restrict__ ei) {
    int e = blockIdx.x * blockDim.x + threadIdx.x;
    if (e >= EE) return;
    int src = ei[e];
    int dst = ei[EE + e];
    int pos = g_rowptr[dst] + atomicAdd(&g_cnt[dst], 1);
    g_csr_src[pos] = src;
}

// ---------------- tf32 tensor-core GEMM (cp.async double-buffered) -----------
__device__ __forceinline__ unsigned f2tf32(float x) {
    unsigned r;
    asm("cvt.rna.tf32.f32 %0, %1;" : "=r"(r) : "f"(x));
    return r;
}

__device__ __forceinline__ void mma_tf32(float* c, const unsigned* a, const unsigned* b) {
    asm volatile(
        "mma.sync.aligned.m16n8k8.row.col.f32.tf32.tf32.f32 "
        "{%0,%1,%2,%3}, {%4,%5,%6,%7}, {%8,%9}, {%0,%1,%2,%3};"
        : "+f"(c[0]), "+f"(c[1]), "+f"(c[2]), "+f"(c[3])
        : "r"(a[0]), "r"(a[1]), "r"(a[2]), "r"(a[3]), "r"(b[0]), "r"(b[1]));
}

__device__ __forceinline__ void cp_async16(float* sdst, const float* gsrc, bool valid) {
    unsigned saddr = (unsigned)__cvta_generic_to_shared(sdst);
    int sz = valid ? 16 : 0;
    asm volatile("cp.async.ca.shared.global [%0], [%1], 16, %2;"
                 :: "r"(saddr), "l"(gsrc), "r"(sz));
}
__device__ __forceinline__ void cp_commit() { asm volatile("cp.async.commit_group;"); }
template <int N> __device__ __forceinline__ void cp_wait() {
    asm volatile("cp.async.wait_group %0;" :: "n"(N));
}

// C[M,NCOLS] = A[M,K] @ W[K,NCOLS] (+bias)(+relu)(*dinv[row])
// BM=128, BK=16. 8 warps: wm 0..3 (32 rows), wn 0..1 (NCOLS/2 cols).
#define ASTRIDE 20
template <int K, int NCOLS, bool RELU, bool BIAS, bool SCALE>
__device__ __forceinline__ void gemm_tf32_body(const float* __restrict__ A,
                                               const float* __restrict__ W,
                                               const float* __restrict__ bias,
                                               float* __restrict__ C) {
    constexpr int BSTRIDE = NCOLS + 8;
    constexpr int NT = NCOLS / 16;          // n8 tiles per warp
    constexpr int WHALF = NCOLS / 2;
    constexpr int BITERS = (4 * NCOLS) / 256;  // float4 chunks of B tile / 256 thr
    constexpr int NK = K / 16;

    __shared__ float As[2][128 * ASTRIDE];
    __shared__ float Bs[2][16 * BSTRIDE];

    const int tid = threadIdx.x;
    const int wid = tid >> 5, lane = tid & 31;
    const int wm = wid & 3, wn = wid >> 2;
    const int g = lane >> 2, t = lane & 3;
    const int m0 = blockIdx.x * 128;

    float acc[2][NT][4];
#pragma unroll
    for (int mt = 0; mt < 2; mt++)
#pragma unroll
        for (int nt = 0; nt < NT; nt++)
#pragma unroll
            for (int i = 0; i < 4; i++) acc[mt][nt][i] = 0.0f;

    // tile loader
    auto load_tiles = [&](int s, int k0) {
#pragma unroll
        for (int i = 0; i < 2; i++) {            // A: 128x16 = 512 float4
            int idx = tid + i * 256;
            int r = idx >> 2, c4 = (idx & 3) * 4;
            int gr = m0 + r;
            bool v = (gr < NN);
            const float* src = A + (size_t)(v ? gr : 0) * K + k0 + c4;
            cp_async16(&As[s][r * ASTRIDE + c4], src, v);
        }
#pragma unroll
        for (int i = 0; i < BITERS; i++) {       // B: 16xNCOLS
            int idx = tid + i * 256;
            int kr = idx / (NCOLS / 4), c4 = (idx % (NCOLS / 4)) * 4;
            cp_async16(&Bs[s][kr * BSTRIDE + c4], W + (size_t)(k0 + kr) * NCOLS + c4, true);
        }
        cp_commit();
    };

    load_tiles(0, 0);
    for (int it = 0; it < NK; it++) {
        int s = it & 1;
        if (it + 1 < NK) {
            load_tiles(s ^ 1, (it + 1) * 16);
            cp_wait<1>();
        } else {
            cp_wait<0>();
        }
        __syncthreads();

#pragma unroll
        for (int ks = 0; ks < 2; ks++) {
            unsigned a[2][4], bf[NT][2];
#pragma unroll
            for (int mt = 0; mt < 2; mt++) {
                int r = wm * 32 + mt * 16 + g;
                int c = ks * 8 + t;
                a[mt][0] = f2tf32(As[s][r * ASTRIDE + c]);
                a[mt][1] = f2tf32(As[s][(r + 8) * ASTRIDE + c]);
                a[mt][2] = f2tf32(As[s][r * ASTRIDE + c + 4]);
                a[mt][3] = f2tf32(As[s][(r + 8) * ASTRIDE + c + 4]);
            }
#pragma unroll
            for (int nt = 0; nt < NT; nt++) {
                int n = wn * WHALF + nt * 8 + g;
                int k = ks * 8 + t;
                bf[nt][0] = f2tf32(Bs[s][k * BSTRIDE + n]);
                bf[nt][1] = f2tf32(Bs[s][(k + 4) * BSTRIDE + n]);
            }
#pragma unroll
            for (int mt = 0; mt < 2; mt++)
#pragma unroll
                for (int nt = 0; nt < NT; nt++) mma_tf32(acc[mt][nt], a[mt], bf[nt]);
        }
        __syncthreads();
    }

    // epilogue
#pragma unroll
    for (int mt = 0; mt < 2; mt++) {
        int rbase = m0 + wm * 32 + mt * 16 + g;
#pragma unroll
        for (int half = 0; half < 2; half++) {
            int r = rbase + half * 8;
            if (r >= NN) continue;
            float s = SCALE ? g_dinv[r] : 1.0f;
#pragma unroll
            for (int nt = 0; nt < NT; nt++) {
                int col = wn * WHALF + nt * 8 + 2 * t;
                float v0 = acc[mt][nt][half * 2 + 0];
                float v1 = acc[mt][nt][half * 2 + 1];
                if (BIAS) { v0 += bias[col]; v1 += bias[col + 1]; }
                if (RELU) { v0 = fmaxf(v0, 0.0f); v1 = fmaxf(v1, 0.0f); }
                if (SCALE) { v0 *= s; v1 *= s; }
                *(float2*)(C + (size_t)r * NCOLS + col) = make_float2(v0, v1);
            }
        }
    }
}

__global__ __launch_bounds__(256) void gemm_pre_kernel(const float* __restrict__ x,
                                                       const float* __restrict__ Wp,
                                                       const float* __restrict__ bp) {
    gemm_tf32_body<DIN, HDIM, true, true, false>(x, Wp, bp, g_h);
}

__global__ __launch_bounds__(256) void gemm_layer_kernel(const float* __restrict__ Wc_i) {
    gemm_tf32_body<HDIM, HDIM, false, false, true>(g_h, Wc_i, nullptr, g_hw);
}

__global__ __launch_bounds__(256) void heads_mid_kernel() {
    gemm_tf32_body<HDIM, MIDC, true, true, false>(g_h, g_w1cat, g_b1cat, g_mid);
}

// ---------------- fused gather + self + bias + BN + relu + residual ----------
__global__ void gather_kernel(const float* __restrict__ bc_i,
                              const float* __restrict__ rmean,
                              const float* __restrict__ rvar,
                              const float* __restrict__ gamma,
                              const float* __restrict__ beta,
                              int residual) {
    int warp = (blockIdx.x * blockDim.x + threadIdx.x) >> 5;
    int l = threadIdx.x & 31;
    if (warp >= NN) return;
    const int n = warp;
    const int c0 = l * 4;

    const float4* hw4 = (const float4*)g_hw;
    float4 acc0 = hw4[(size_t)n * 32 + l];  // self term (pre-scaled by dinv[n])
    float4 acc1 = make_float4(0.f, 0.f, 0.f, 0.f);

    int j = g_rowptr[n];
    const int end = g_rowptr[n + 1];
    for (; j + 8 <= end; j += 8) {
        int s0 = __ldg(&g_csr_src[j + 0]);
        int s1 = __ldg(&g_csr_src[j + 1]);
        int s2 = __ldg(&g_csr_src[j + 2]);
        int s3 = __ldg(&g_csr_src[j + 3]);
        int s4 = __ldg(&g_csr_src[j + 4]);
        int s5 = __ldg(&g_csr_src[j + 5]);
        int s6 = __ldg(&g_csr_src[j + 6]);
        int s7 = __ldg(&g_csr_src[j + 7]);
        float4 v0 = hw4[(size_t)s0 * 32 + l];
        float4 v1 = hw4[(size_t)s1 * 32 + l];
        float4 v2 = hw4[(size_t)s2 * 32 + l];
        float4 v3 = hw4[(size_t)s3 * 32 + l];
        float4 v4 = hw4[(size_t)s4 * 32 + l];
        float4 v5 = hw4[(size_t)s5 * 32 + l];
        float4 v6 = hw4[(size_t)s6 * 32 + l];
        float4 v7 = hw4[(size_t)s7 * 32 + l];
        acc0.x += v0.x + v1.x + v2.x + v3.x;
        acc0.y += v0.y + v1.y + v2.y + v3.y;
        acc0.z += v0.z + v1.z + v2.z + v3.z;
        acc0.w += v0.w + v1.w + v2.w + v3.w;
        acc1.x += v4.x + v5.x + v6.x + v7.x;
        acc1.y += v4.y + v5.y + v6.y + v7.y;
        acc1.z += v4.z + v5.z + v6.z + v7.z;
        acc1.w += v4.w + v5.w + v6.w + v7.w;
    }
    for (; j < end; j++) {
        int s = __ldg(&g_csr_src[j]);
        float4 v = hw4[(size_t)s * 32 + l];
        acc1.x += v.x; acc1.y += v.y; acc1.z += v.z; acc1.w += v.w;
    }
    float4 acc = make_float4(acc0.x + acc1.x, acc0.y + acc1.y,
                             acc0.z + acc1.z, acc0.w + acc1.w);

    const float dn = g_dinv[n];
    float4 bc4 = *(const float4*)(bc_i + c0);
    float4 rm4 = *(const float4*)(rmean + c0);
    float4 rv4 = *(const float4*)(rvar + c0);
    float4 ga4 = *(const float4*)(gamma + c0);
    float4 be4 = *(const float4*)(beta + c0);

    float4 o;
    o.x = fmaxf((acc.x * dn + bc4.x - rm4.x) * rsqrtf(rv4.x + EPSBN) * ga4.x + be4.x, 0.0f);
    o.y = fmaxf((acc.y * dn + bc4.y - rm4.y) * rsqrtf(rv4.y + EPSBN) * ga4.y + be4.y, 0.0f);
    o.z = fmaxf((acc.z * dn + bc4.z - rm4.z) * rsqrtf(rv4.z + EPSBN) * ga4.z + be4.z, 0.0f);
    o.w = fmaxf((acc.w * dn + bc4.w - rm4.w) * rsqrtf(rv4.w + EPSBN) * ga4.w + be4.w, 0.0f);

    float4* h4 = (float4*)g_h;
    if (residual) {
        float4 hp = h4[(size_t)n * 32 + l];
        o.x += hp.x; o.y += hp.y; o.z += hp.z; o.w += hp.w;
    }
    h4[(size_t)n * 32 + l] = o;
}

// ---------------- heads second layer ------------------------------------------
// out layout: [0,N) risk_scores ; [N,5N) risk_logits [N,4] ; [5N,6N) relevance
__global__ void heads_out_kernel(const float* __restrict__ rs_W2, const float* __restrict__ rs_b2,
                                 const float* __restrict__ rl_W2, const float* __restrict__ rl_b2,
                                 const float* __restrict__ rel_W2, const float* __restrict__ rel_b2,
                                 float* __restrict__ out) {
    __shared__ float w_rs[HHALF];
    __shared__ float w_rl[HHALF * NRL];
    __shared__ float w_rel[HHALF];
    __shared__ float bsm[8];   // [0]=rs_b2, [1..4]=rl_b2, [5]=rel_b2

    const int tid = threadIdx.x;
    if (tid < HHALF) { w_rs[tid] = rs_W2[tid]; w_rel[tid] = rel_W2[tid]; }
    if (tid < HHALF * NRL) w_rl[tid] = rl_W2[tid];
    if (tid == 0) { bsm[0] = rs_b2[0]; bsm[5] = rel_b2[0]; }
    if (tid < NRL) bsm[1 + tid] = rl_b2[tid];
    __syncthreads();

    const int warp = (blockIdx.x * (blockDim.x >> 5)) + (tid >> 5);
    const int l = tid & 31;
    if (warp >= NN) return;
    const int n = warp;

    const float* m = g_mid + (size_t)n * MIDC;
    float m0 = m[l],        m1 = m[l + 32];
    float m2 = m[l + 64],   m3 = m[l + 96];
    float m4 = m[l + 128],  m5 = m[l + 160];

    float prs = m0 * w_rs[l] + m1 * w_rs[l + 32];
    float prel = m4 * w_rel[l] + m5 * w_rel[l + 32];
    float prl[NRL];
#pragma unroll
    for (int j = 0; j < NRL; j++)
        prl[j] = m2 * w_rl[l * NRL + j] + m3 * w_rl[(l + 32) * NRL + j];

#pragma unroll
    for (int o = 16; o; o >>= 1) {
        prs += __shfl_xor_sync(0xffffffffu, prs, o);
        prel += __shfl_xor_sync(0xffffffffu, prel, o);
#pragma unroll
        for (int j = 0; j < NRL; j++) prl[j] += __shfl_xor_sync(0xffffffffu, prl[j], o);
    }
    if (l == 0) {
        out[n] = 1.0f / (1.0f + expf(-(prs + bsm[0])));
#pragma unroll
        for (int j = 0; j < NRL; j++)
            out[(size_t)NN + (size_t)n * NRL + j] = prl[j] + bsm[1 + j];
        out[(size_t)5 * NN + n] = 1.0f / (1.0f + expf(-(prel + bsm[5])));
    }
}

// ---------------- launch ------------------------------------------------------
extern "C" void kernel_launch(void* const* d_in, const int* in_sizes, int n_in,
                              void* d_out, int out_size) {
    const float* x      = (const float*)d_in[0];
    const int*   ei     = (const int*)  d_in[1];
    const float* Wp     = (const float*)d_in[2];
    const float* bp     = (const float*)d_in[3];
    const float* Wc     = (const float*)d_in[4];
    const float* bc     = (const float*)d_in[5];
    const float* gamma  = (const float*)d_in[6];
    const float* beta   = (const float*)d_in[7];
    const float* rmean  = (const float*)d_in[8];
    const float* rvar   = (const float*)d_in[9];
    const float* rel_W1 = (const float*)d_in[10];
    const float* rel_b1 = (const float*)d_in[11];
    const float* rel_W2 = (const float*)d_in[12];
    const float* rel_b2 = (const float*)d_in[13];
    const float* rs_W1  = (const float*)d_in[14];
    const float* rs_b1  = (const float*)d_in[15];
    const float* rs_W2  = (const float*)d_in[16];
    const float* rs_b2  = (const float*)d_in[17];
    const float* rl_W1  = (const float*)d_in[18];
    const float* rl_b1  = (const float*)d_in[19];
    const float* rl_W2  = (const float*)d_in[20];
    const float* rl_b2  = (const float*)d_in[21];
    float* out = (float*)d_out;

    const int T = 256;
    const int gemm_blocks = (NN + 127) / 128;  // 782

    // 1..3: independent prep (deg_count must precede scan; gemm_pre is launch #4 for ncu)
    deg_init_kernel<<<(NN + T - 1) / T, T>>>();
    deg_count_kernel<<<(EE + T - 1) / T, T>>>(ei);
    w1cat_kernel<<<(HDIM * MIDC + T - 1) / T, T>>>(rs_W1, rs_b1, rl_W1, rl_b1, rel_W1, rel_b1);
    gemm_pre_kernel<<<gemm_blocks, 256>>>(x, Wp, bp);   // launch #4 (profiled)

    scan_partial_kernel<<<SCAN_NB, 512>>>();
    scan_bsum_kernel<<<1, 256>>>();
    scan_fill_kernel<<<SCAN_NB, 512>>>();
    csr_fill_kernel<<<(EE + T - 1) / T, T>>>(ei);

    const int gather_blocks = (NN * 32 + T - 1) / T;  // 12500
    for (int i = 0; i < NLAYERS; i++) {
        gemm_layer_kernel<<<gemm_blocks, 256>>>(Wc + (size_t)i * HDIM * HDIM);
        gather_kernel<<<gather_blocks, T>>>(bc + (size_t)i * HDIM,
                                            rmean + (size_t)i * HDIM,
                                            rvar + (size_t)i * HDIM,
                                            gamma + (size_t)i * HDIM,
                                            beta + (size_t)i * HDIM,
                                            i > 0 ? 1 : 0);
    }

    heads_mid_kernel<<<gemm_blocks, 256>>>();
    heads_out_kernel<<<(NN * 32 + T - 1) / T, T>>>(rs_W2, rs_b2, rl_W2, rl_b2,
                                                   rel_W2, rel_b2, out);
}

// round 7
// speedup vs baseline: 4.3305x; 1.0569x over previous
#include <cuda_runtime.h>
#include <math.h>

#define NN 100000
#define EE 1600000
#define DIN 384
#define HDIM 128
#define HHALF 64
#define NLAYERS 3
#define NRL 4
#define EPSBN 1e-5f

#define SCAN_NB 200
#define SCAN_CHUNK 500

#define MIDC 192   // concatenated heads hidden width

// ---------------- scratch (device globals; no allocation allowed) ------------
__device__ float g_h[NN * HDIM];     // current node features (tf32-rounded)
__device__ float g_hw[NN * HDIM];    // (h @ Wc[i]) * dinv[row]
__device__ float g_mid[NN * MIDC];   // heads hidden
__device__ float g_w1cat[HDIM * MIDC];
__device__ float g_b1cat[MIDC];
__device__ float g_wp_r[DIN * HDIM];          // tf32-rounded Wp
__device__ float g_wc_r[NLAYERS * HDIM * HDIM]; // tf32-rounded Wc
__device__ float g_dinv[NN];
__device__ int   g_cnt[NN];
__device__ int   g_rowptr[NN + 1];
__device__ int   g_csr_src[EE];
__device__ int   g_bsum[SCAN_NB];
__device__ int   g_boff[SCAN_NB];

__device__ __forceinline__ unsigned f2tf32(float x) {
    unsigned r;
    asm("cvt.rna.tf32.f32 %0, %1;" : "=r"(r) : "f"(x));
    return r;
}
__device__ __forceinline__ float tf32round(float x) {
    return __uint_as_float(f2tf32(x));
}

// ---------------- weight prep: tf32 pre-rounding -----------------------------
// DIN*HDIM == NLAYERS*HDIM*HDIM == 49152 (handy coincidence)
__global__ void round_weights_kernel(const float* __restrict__ Wp,
                                     const float* __restrict__ Wc) {
    int idx = blockIdx.x * blockDim.x + threadIdx.x;
    if (idx >= DIN * HDIM) return;
    g_wp_r[idx] = tf32round(Wp[idx]);
    g_wc_r[idx] = tf32round(Wc[idx]);
}

// ---------------- heads weight concat (tf32-rounded) --------------------------
__global__ void w1cat_kernel(const float* __restrict__ rs_W1, const float* __restrict__ rs_b1,
                             const float* __restrict__ rl_W1, const float* __restrict__ rl_b1,
                             const float* __restrict__ rel_W1, const float* __restrict__ rel_b1) {
    int idx = blockIdx.x * blockDim.x + threadIdx.x;   // [0, 128*192)
    if (idx >= HDIM * MIDC) return;
    int k = idx / MIDC, c = idx % MIDC;
    int head = c >> 6, j = c & 63;
    const float* W1 = (head == 0) ? rs_W1 : (head == 1) ? rl_W1 : rel_W1;
    g_w1cat[idx] = tf32round(W1[k * HHALF + j]);
    if (k == 0) {
        const float* B1 = (head == 0) ? rs_b1 : (head == 1) ? rl_b1 : rel_b1;
        g_b1cat[c] = B1[j];
    }
}

// ---------------- degree count ------------------------------------------------
__global__ void deg_init_kernel() {
    int i = blockIdx.x * blockDim.x + threadIdx.x;
    if (i < NN) g_cnt[i] = 0;
}

__global__ void deg_count_kernel(const int* __restrict__ ei) {
    int e = blockIdx.x * blockDim.x + threadIdx.x;
    if (e < EE) atomicAdd(&g_cnt[ei[EE + e]], 1);
}

// ---------------- 3-phase parallel scan --------------------------------------
__global__ void scan_partial_kernel() {   // grid SCAN_NB, block 512
    __shared__ int sh[512];
    int b = blockIdx.x, t = threadIdx.x;
    int i = b * SCAN_CHUNK + t;
    sh[t] = (t < SCAN_CHUNK) ? g_cnt[i] : 0;
    __syncthreads();
#pragma unroll
    for (int o = 256; o; o >>= 1) {
        if (t < o) sh[t] += sh[t + o];
        __syncthreads();
    }
    if (t == 0) g_bsum[b] = sh[0];
}

__global__ void scan_bsum_kernel() {      // 1 block, 256 threads
    __shared__ int sh[256];
    int t = threadIdx.x;
    sh[t] = (t < SCAN_NB) ? g_bsum[t] : 0;
    __syncthreads();
#pragma unroll
    for (int o = 1; o < 256; o <<= 1) {
        int v = (t >= o) ? sh[t - o] : 0;
        __syncthreads();
        sh[t] += v;
        __syncthreads();
    }
    if (t < SCAN_NB) g_boff[t] = (t ? sh[t - 1] : 0);
    if (t == 0) g_rowptr[NN] = EE;
}

__global__ void scan_fill_kernel() {      // grid SCAN_NB, block 512
    __shared__ int sh[512];
    int b = blockIdx.x, t = threadIdx.x;
    int i = b * SCAN_CHUNK + t;
    int c = (t < SCAN_CHUNK) ? g_cnt[i] : 0;
    sh[t] = c;
    __syncthreads();
#pragma unroll
    for (int o = 1; o < 512; o <<= 1) {
        int v = (t >= o) ? sh[t - o] : 0;
        __syncthreads();
        sh[t] += v;
        __syncthreads();
    }
    if (t < SCAN_CHUNK) {
        g_rowptr[i] = g_boff[b] + sh[t] - c;    // exclusive
        g_cnt[i] = 0;
        g_dinv[i] = rsqrtf((float)(c + 1));     // deg = in-degree + self loop
    }
}

__global__ void csr_fill_kernel(const int* __restrict__ ei) {
    int e = blockIdx.x * blockDim.x + threadIdx.x;
    if (e >= EE) return;
    int src = ei[e];
    int dst = ei[EE + e];
    int pos = g_rowptr[dst] + atomicAdd(&g_cnt[dst], 1);
    g_csr_src[pos] = src;
}

// ---------------- tf32 tensor-core GEMM v3 ------------------------------------
__device__ __forceinline__ void mma_tf32(float* c, const unsigned* a, const unsigned* b) {
    asm volatile(
        "mma.sync.aligned.m16n8k8.row.col.f32.tf32.tf32.f32 "
        "{%0,%1,%2,%3}, {%4,%5,%6,%7}, {%8,%9}, {%0,%1,%2,%3};"
        : "+f"(c[0]), "+f"(c[1]), "+f"(c[2]), "+f"(c[3])
        : "r"(a[0]), "r"(a[1]), "r"(a[2]), "r"(a[3]), "r"(b[0]), "r"(b[1]));
}

__device__ __forceinline__ void cp_async16(float* sdst, const float* gsrc, bool valid) {
    unsigned saddr = (unsigned)__cvta_generic_to_shared(sdst);
    int sz = valid ? 16 : 0;
    asm volatile("cp.async.ca.shared.global [%0], [%1], 16, %2;"
                 :: "r"(saddr), "l"(gsrc), "r"(sz));
}
__device__ __forceinline__ void cp_commit() { asm volatile("cp.async.commit_group;"); }
template <int N> __device__ __forceinline__ void cp_wait() {
    asm volatile("cp.async.wait_group %0;" :: "n"(N));
}

// C[M,NCOLS] = A[M,K] @ W[K,NCOLS] (+bias)(+relu)(*dinv[row])(tf32-round out)
// BM=128, BK=16. WM x WN warps; warp tile (128/WM) x (NCOLS/WN).
// ACVT: cvt.rna A operands in-loop (raw fp32 A). Otherwise A assumed pre-rounded.
// B (weights) always assumed pre-rounded -> raw-bit truncation is exact rna.
#define ASTRIDE 20
template <int K, int NCOLS, int WM, int WN,
          bool ACVT, bool RELU, bool BIAS, bool SCALE, bool ROUND_OUT>
__device__ __forceinline__ void gemm_tf32_body(const float* __restrict__ A,
                                               const float* __restrict__ W,
                                               const float* __restrict__ bias,
                                               float* __restrict__ C) {
    constexpr int THREADS = WM * WN * 32;
    constexpr int MT = 128 / (16 * WM);
    constexpr int NT = NCOLS / (8 * WN);
    constexpr int BSTRIDE = NCOLS + 8;
    constexpr int NK = K / 16;

    __shared__ float As[2][128 * ASTRIDE];
    __shared__ float Bs[2][16 * BSTRIDE];

    const int tid = threadIdx.x;
    const int wid = tid >> 5, lane = tid & 31;
    const int wm = wid % WM, wn = wid / WM;
    const int g = lane >> 2, t = lane & 3;
    const int m0 = blockIdx.x * 128;

    float acc[MT][NT][4];
#pragma unroll
    for (int mt = 0; mt < MT; mt++)
#pragma unroll
        for (int nt = 0; nt < NT; nt++)
#pragma unroll
            for (int i = 0; i < 4; i++) acc[mt][nt][i] = 0.0f;

    auto load_tiles = [&](int s, int k0) {
#pragma unroll
        for (int idx = tid; idx < 512; idx += THREADS) {   // A: 128x16 = 512 float4
            int r = idx >> 2, c4 = (idx & 3) * 4;
            int gr = m0 + r;
            bool v = (gr < NN);
            const float* src = A + (size_t)(v ? gr : 0) * K + k0 + c4;
            cp_async16(&As[s][r * ASTRIDE + c4], src, v);
        }
#pragma unroll
        for (int idx = tid; idx < 4 * NCOLS; idx += THREADS) {  // B: 16xNCOLS
            int kr = idx / (NCOLS / 4), c4 = (idx % (NCOLS / 4)) * 4;
            cp_async16(&Bs[s][kr * BSTRIDE + c4], W + (size_t)(k0 + kr) * NCOLS + c4, true);
        }
        cp_commit();
    };

    load_tiles(0, 0);
    for (int it = 0; it < NK; it++) {
        int s = it & 1;
        if (it + 1 < NK) {
            load_tiles(s ^ 1, (it + 1) * 16);
            cp_wait<1>();
        } else {
            cp_wait<0>();
        }
        __syncthreads();

#pragma unroll
        for (int ks = 0; ks < 2; ks++) {
            unsigned a[MT][4], bf[NT][2];
#pragma unroll
            for (int mt = 0; mt < MT; mt++) {
                int r = wm * (16 * MT) + mt * 16 + g;
                int c = ks * 8 + t;
                float a0 = As[s][r * ASTRIDE + c];
                float a1 = As[s][(r + 8) * ASTRIDE + c];
                float a2 = As[s][r * ASTRIDE + c + 4];
                float a3 = As[s][(r + 8) * ASTRIDE + c + 4];
                if (ACVT) {
                    a[mt][0] = f2tf32(a0); a[mt][1] = f2tf32(a1);
                    a[mt][2] = f2tf32(a2); a[mt][3] = f2tf32(a3);
                } else {
                    a[mt][0] = __float_as_uint(a0); a[mt][1] = __float_as_uint(a1);
                    a[mt][2] = __float_as_uint(a2); a[mt][3] = __float_as_uint(a3);
                }
            }
#pragma unroll
            for (int nt = 0; nt < NT; nt++) {
                int n = wn * (8 * NT) + nt * 8 + g;
                int k = ks * 8 + t;
                bf[nt][0] = __float_as_uint(Bs[s][k * BSTRIDE + n]);
                bf[nt][1] = __float_as_uint(Bs[s][(k + 4) * BSTRIDE + n]);
            }
#pragma unroll
            for (int mt = 0; mt < MT; mt++)
#pragma unroll
                for (int nt = 0; nt < NT; nt++) mma_tf32(acc[mt][nt], a[mt], bf[nt]);
        }
        __syncthreads();
    }

    // epilogue
#pragma unroll
    for (int mt = 0; mt < MT; mt++) {
        int rbase = m0 + wm * (16 * MT) + mt * 16 + g;
#pragma unroll
        for (int half = 0; half < 2; half++) {
            int r = rbase + half * 8;
            if (r >= NN) continue;
            float sc = SCALE ? g_dinv[r] : 1.0f;
#pragma unroll
            for (int nt = 0; nt < NT; nt++) {
                int col = wn * (8 * NT) + nt * 8 + 2 * t;
                float v0 = acc[mt][nt][half * 2 + 0];
                float v1 = acc[mt][nt][half * 2 + 1];
                if (BIAS) { v0 += bias[col]; v1 += bias[col + 1]; }
                if (RELU) { v0 = fmaxf(v0, 0.0f); v1 = fmaxf(v1, 0.0f); }
                if (SCALE) { v0 *= sc; v1 *= sc; }
                if (ROUND_OUT) { v0 = tf32round(v0); v1 = tf32round(v1); }
                *(float2*)(C + (size_t)r * NCOLS + col) = make_float2(v0, v1);
            }
        }
    }
}

// gemm_pre: A = x (raw fp32 -> in-loop cvt), out g_h tf32-rounded
__global__ __launch_bounds__(128, 2) void gemm_pre_kernel(const float* __restrict__ x,
                                                          const float* __restrict__ bp) {
    gemm_tf32_body<DIN, HDIM, 2, 2, true, true, true, false, true>(x, g_wp_r, bp, g_h);
}

// layer GEMM: A = g_h (pre-rounded), B = g_wc_r, out g_hw (fp32, scaled by dinv)
__global__ __launch_bounds__(128, 2) void gemm_layer_kernel(int layer) {
    gemm_tf32_body<HDIM, HDIM, 2, 2, false, false, false, true, false>(
        g_h, g_wc_r + (size_t)layer * HDIM * HDIM, nullptr, g_hw);
}

// heads hidden: A = g_h (pre-rounded), B = g_w1cat (pre-rounded), out g_mid fp32
__global__ __launch_bounds__(256) void heads_mid_kernel() {
    gemm_tf32_body<HDIM, MIDC, 4, 2, false, true, true, false, false>(
        g_h, g_w1cat, g_b1cat, g_mid);
}

// ---------------- fused gather + self + bias + BN + relu + residual ----------
__global__ void gather_kernel(const float* __restrict__ bc_i,
                              const float* __restrict__ rmean,
                              const float* __restrict__ rvar,
                              const float* __restrict__ gamma,
                              const float* __restrict__ beta,
                              int residual) {
    int warp = (blockIdx.x * blockDim.x + threadIdx.x) >> 5;
    int l = threadIdx.x & 31;
    if (warp >= NN) return;
    const int n = warp;
    const int c0 = l * 4;

    const float4* hw4 = (const float4*)g_hw;
    float4 acc0 = hw4[(size_t)n * 32 + l];  // self term (pre-scaled by dinv[n])
    float4 acc1 = make_float4(0.f, 0.f, 0.f, 0.f);

    int j = g_rowptr[n];
    const int end = g_rowptr[n + 1];
    for (; j + 8 <= end; j += 8) {
        int s0 = __ldg(&g_csr_src[j + 0]);
        int s1 = __ldg(&g_csr_src[j + 1]);
        int s2 = __ldg(&g_csr_src[j + 2]);
        int s3 = __ldg(&g_csr_src[j + 3]);
        int s4 = __ldg(&g_csr_src[j + 4]);
        int s5 = __ldg(&g_csr_src[j + 5]);
        int s6 = __ldg(&g_csr_src[j + 6]);
        int s7 = __ldg(&g_csr_src[j + 7]);
        float4 v0 = hw4[(size_t)s0 * 32 + l];
        float4 v1 = hw4[(size_t)s1 * 32 + l];
        float4 v2 = hw4[(size_t)s2 * 32 + l];
        float4 v3 = hw4[(size_t)s3 * 32 + l];
        float4 v4 = hw4[(size_t)s4 * 32 + l];
        float4 v5 = hw4[(size_t)s5 * 32 + l];
        float4 v6 = hw4[(size_t)s6 * 32 + l];
        float4 v7 = hw4[(size_t)s7 * 32 + l];
        acc0.x += v0.x + v1.x + v2.x + v3.x;
        acc0.y += v0.y + v1.y + v2.y + v3.y;
        acc0.z += v0.z + v1.z + v2.z + v3.z;
        acc0.w += v0.w + v1.w + v2.w + v3.w;
        acc1.x += v4.x + v5.x + v6.x + v7.x;
        acc1.y += v4.y + v5.y + v6.y + v7.y;
        acc1.z += v4.z + v5.z + v6.z + v7.z;
        acc1.w += v4.w + v5.w + v6.w + v7.w;
    }
    for (; j < end; j++) {
        int s = __ldg(&g_csr_src[j]);
        float4 v = hw4[(size_t)s * 32 + l];
        acc1.x += v.x; acc1.y += v.y; acc1.z += v.z; acc1.w += v.w;
    }
    float4 acc = make_float4(acc0.x + acc1.x, acc0.y + acc1.y,
                             acc0.z + acc1.z, acc0.w + acc1.w);

    const float dn = g_dinv[n];
    float4 bc4 = *(const float4*)(bc_i + c0);
    float4 rm4 = *(const float4*)(rmean + c0);
    float4 rv4 = *(const float4*)(rvar + c0);
    float4 ga4 = *(const float4*)(gamma + c0);
    float4 be4 = *(const float4*)(beta + c0);

    float4 o;
    o.x = fmaxf((acc.x * dn + bc4.x - rm4.x) * rsqrtf(rv4.x + EPSBN) * ga4.x + be4.x, 0.0f);
    o.y = fmaxf((acc.y * dn + bc4.y - rm4.y) * rsqrtf(rv4.y + EPSBN) * ga4.y + be4.y, 0.0f);
    o.z = fmaxf((acc.z * dn + bc4.z - rm4.z) * rsqrtf(rv4.z + EPSBN) * ga4.z + be4.z, 0.0f);
    o.w = fmaxf((acc.w * dn + bc4.w - rm4.w) * rsqrtf(rv4.w + EPSBN) * ga4.w + be4.w, 0.0f);

    float4* h4 = (float4*)g_h;
    if (residual) {
        float4 hp = h4[(size_t)n * 32 + l];
        o.x += hp.x; o.y += hp.y; o.z += hp.z; o.w += hp.w;
    }
    // tf32-round so downstream GEMMs can consume raw bits (exact rna)
    o.x = tf32round(o.x); o.y = tf32round(o.y);
    o.z = tf32round(o.z); o.w = tf32round(o.w);
    h4[(size_t)n * 32 + l] = o;
}

// ---------------- heads second layer ------------------------------------------
// out layout: [0,N) risk_scores ; [N,5N) risk_logits [N,4] ; [5N,6N) relevance
__global__ void heads_out_kernel(const float* __restrict__ rs_W2, const float* __restrict__ rs_b2,
                                 const float* __restrict__ rl_W2, const float* __restrict__ rl_b2,
                                 const float* __restrict__ rel_W2, const float* __restrict__ rel_b2,
                                 float* __restrict__ out) {
    __shared__ float w_rs[HHALF];
    __shared__ float w_rl[HHALF * NRL];
    __shared__ float w_rel[HHALF];
    __shared__ float bsm[8];   // [0]=rs_b2, [1..4]=rl_b2, [5]=rel_b2

    const int tid = threadIdx.x;
    if (tid < HHALF) { w_rs[tid] = rs_W2[tid]; w_rel[tid] = rel_W2[tid]; }
    if (tid < HHALF * NRL) w_rl[tid] = rl_W2[tid];
    if (tid == 0) { bsm[0] = rs_b2[0]; bsm[5] = rel_b2[0]; }
    if (tid < NRL) bsm[1 + tid] = rl_b2[tid];
    __syncthreads();

    const int warp = (blockIdx.x * (blockDim.x >> 5)) + (tid >> 5);
    const int l = tid & 31;
    if (warp >= NN) return;
    const int n = warp;

    const float* m = g_mid + (size_t)n * MIDC;
    float m0 = m[l],        m1 = m[l + 32];
    float m2 = m[l + 64],   m3 = m[l + 96];
    float m4 = m[l + 128],  m5 = m[l + 160];

    float prs = m0 * w_rs[l] + m1 * w_rs[l + 32];
    float prel = m4 * w_rel[l] + m5 * w_rel[l + 32];
    float prl[NRL];
#pragma unroll
    for (int j = 0; j < NRL; j++)
        prl[j] = m2 * w_rl[l * NRL + j] + m3 * w_rl[(l + 32) * NRL + j];

#pragma unroll
    for (int o = 16; o; o >>= 1) {
        prs += __shfl_xor_sync(0xffffffffu, prs, o);
        prel += __shfl_xor_sync(0xffffffffu, prel, o);
#pragma unroll
        for (int j = 0; j < NRL; j++) prl[j] += __shfl_xor_sync(0xffffffffu, prl[j], o);
    }
    if (l == 0) {
        out[n] = 1.0f / (1.0f + expf(-(prs + bsm[0])));
#pragma unroll
        for (int j = 0; j < NRL; j++)
            out[(size_t)NN + (size_t)n * NRL + j] = prl[j] + bsm[1 + j];
        out[(size_t)5 * NN + n] = 1.0f / (1.0f + expf(-(prel + bsm[5])));
    }
}

// ---------------- launch ------------------------------------------------------
extern "C" void kernel_launch(void* const* d_in, const int* in_sizes, int n_in,
                              void* d_out, int out_size) {
    const float* x      = (const float*)d_in[0];
    const int*   ei     = (const int*)  d_in[1];
    const float* Wp     = (const float*)d_in[2];
    const float* bp     = (const float*)d_in[3];
    const float* Wc     = (const float*)d_in[4];
    const float* bc     = (const float*)d_in[5];
    const float* gamma  = (const float*)d_in[6];
    const float* beta   = (const float*)d_in[7];
    const float* rmean  = (const float*)d_in[8];
    const float* rvar   = (const float*)d_in[9];
    const float* rel_W1 = (const float*)d_in[10];
    const float* rel_b1 = (const float*)d_in[11];
    const float* rel_W2 = (const float*)d_in[12];
    const float* rel_b2 = (const float*)d_in[13];
    const float* rs_W1  = (const float*)d_in[14];
    const float* rs_b1  = (const float*)d_in[15];
    const float* rs_W2  = (const float*)d_in[16];
    const float* rs_b2  = (const float*)d_in[17];
    const float* rl_W1  = (const float*)d_in[18];
    const float* rl_b1  = (const float*)d_in[19];
    const float* rl_W2  = (const float*)d_in[20];
    const float* rl_b2  = (const float*)d_in[21];
    float* out = (float*)d_out;

    const int T = 256;
    const int gemm_blocks = (NN + 127) / 128;  // 782

    // launches 1-3: prep; launch 4 = gemm_pre (profiled slot)
    deg_init_kernel<<<(NN + T - 1) / T, T>>>();
    deg_count_kernel<<<(EE + T - 1) / T, T>>>(ei);
    round_weights_kernel<<<(DIN * HDIM + T - 1) / T, T>>>(Wp, Wc);
    gemm_pre_kernel<<<gemm_blocks, 128>>>(x, bp);

    scan_partial_kernel<<<SCAN_NB, 512>>>();
    scan_bsum_kernel<<<1, 256>>>();
    scan_fill_kernel<<<SCAN_NB, 512>>>();
    csr_fill_kernel<<<(EE + T - 1) / T, T>>>(ei);
    w1cat_kernel<<<(HDIM * MIDC + T - 1) / T, T>>>(rs_W1, rs_b1, rl_W1, rl_b1, rel_W1, rel_b1);

    const int gather_blocks = (NN * 32 + T - 1) / T;  // 12500
    for (int i = 0; i < NLAYERS; i++) {
        gemm_layer_kernel<<<gemm_blocks, 128>>>(i);
        gather_kernel<<<gather_blocks, T>>>(bc + (size_t)i * HDIM,
                                            rmean + (size_t)i * HDIM,
                                            rvar + (size_t)i * HDIM,
                                            gamma + (size_t)i * HDIM,
                                            beta + (size_t)i * HDIM,
                                            i > 0 ? 1 : 0);
    }

    heads_mid_kernel<<<gemm_blocks, 256>>>();
    heads_out_kernel<<<(NN * 32 + T - 1) / T, T>>>(rs_W2, rs_b2, rl_W2, rl_b2,
                                                   rel_W2, rel_b2, out);
}

// round 9
// speedup vs baseline: 4.7803x; 1.1039x over previous
#include <cuda_runtime.h>
#include <cuda_fp16.h>
#include <math.h>

#define NN 100000
#define EE 1600000
#define DIN 384
#define HDIM 128
#define HHALF 64
#define NLAYERS 3
#define NRL 4
#define EPSBN 1e-5f

#define SCAN_NB 200
#define SCAN_CHUNK 500

#define MIDC 192   // concatenated heads hidden width

// ---------------- scratch (device globals; no allocation allowed) ------------
__device__ float   g_h[NN * HDIM];      // current node features (tf32-rounded)
__device__ __half2 g_hw2[NN * HDIM / 2]; // (h @ Wc[i]) * dinv[row], fp16
__device__ float   g_mid[NN * MIDC];    // heads hidden
__device__ float   g_w1cat[HDIM * MIDC];
__device__ float   g_b1cat[MIDC];
__device__ float   g_wp_r[DIN * HDIM];            // tf32-rounded Wp
__device__ float   g_wc_r[NLAYERS * HDIM * HDIM]; // tf32-rounded Wc
__device__ float   g_dinv[NN];
__device__ int     g_cnt[NN];
__device__ int     g_rowptr[NN + 1];
__device__ int     g_csr_src[EE];
__device__ int     g_bsum[SCAN_NB];
__device__ int     g_boff[SCAN_NB];

__device__ __forceinline__ unsigned f2tf32(float x) {
    unsigned r;
    asm("cvt.rna.tf32.f32 %0, %1;" : "=r"(r) : "f"(x));
    return r;
}
__device__ __forceinline__ float tf32round(float x) {
    return __uint_as_float(f2tf32(x));
}

// ---------------- weight prep: tf32 pre-rounding -----------------------------
__global__ void round_weights_kernel(const float* __restrict__ Wp,
                                     const float* __restrict__ Wc) {
    int idx = blockIdx.x * blockDim.x + threadIdx.x;
    if (idx >= DIN * HDIM) return;
    g_wp_r[idx] = tf32round(Wp[idx]);
    g_wc_r[idx] = tf32round(Wc[idx]);
}

// ---------------- heads weight concat (tf32-rounded) --------------------------
__global__ void w1cat_kernel(const float* __restrict__ rs_W1, const float* __restrict__ rs_b1,
                             const float* __restrict__ rl_W1, const float* __restrict__ rl_b1,
                             const float* __restrict__ rel_W1, const float* __restrict__ rel_b1) {
    int idx = blockIdx.x * blockDim.x + threadIdx.x;   // [0, 128*192)
    if (idx >= HDIM * MIDC) return;
    int k = idx / MIDC, c = idx % MIDC;
    int head = c >> 6, j = c & 63;
    const float* W1 = (head == 0) ? rs_W1 : (head == 1) ? rl_W1 : rel_W1;
    g_w1cat[idx] = tf32round(W1[k * HHALF + j]);
    if (k == 0) {
        const float* B1 = (head == 0) ? rs_b1 : (head == 1) ? rl_b1 : rel_b1;
        g_b1cat[c] = B1[j];
    }
}

// ---------------- degree count ------------------------------------------------
__global__ void deg_init_kernel() {
    int i = blockIdx.x * blockDim.x + threadIdx.x;
    if (i < NN) g_cnt[i] = 0;
}

__global__ void deg_count_kernel(const int* __restrict__ ei) {
    int e = blockIdx.x * blockDim.x + threadIdx.x;
    if (e < EE) atomicAdd(&g_cnt[ei[EE + e]], 1);
}

// ---------------- 3-phase parallel scan --------------------------------------
__global__ void scan_partial_kernel() {   // grid SCAN_NB, block 512
    __shared__ int sh[512];
    int b = blockIdx.x, t = threadIdx.x;
    int i = b * SCAN_CHUNK + t;
    sh[t] = (t < SCAN_CHUNK) ? g_cnt[i] : 0;
    __syncthreads();
#pragma unroll
    for (int o = 256; o; o >>= 1) {
        if (t < o) sh[t] += sh[t + o];
        __syncthreads();
    }
    if (t == 0) g_bsum[b] = sh[0];
}

__global__ void scan_bsum_kernel() {      // 1 block, 256 threads
    __shared__ int sh[256];
    int t = threadIdx.x;
    sh[t] = (t < SCAN_NB) ? g_bsum[t] : 0;
    __syncthreads();
#pragma unroll
    for (int o = 1; o < 256; o <<= 1) {
        int v = (t >= o) ? sh[t - o] : 0;
        __syncthreads();
        sh[t] += v;
        __syncthreads();
    }
    if (t < SCAN_NB) g_boff[t] = (t ? sh[t - 1] : 0);
    if (t == 0) g_rowptr[NN] = EE;
}

__global__ void scan_fill_kernel() {      // grid SCAN_NB, block 512
    __shared__ int sh[512];
    int b = blockIdx.x, t = threadIdx.x;
    int i = b * SCAN_CHUNK + t;
    int c = (t < SCAN_CHUNK) ? g_cnt[i] : 0;
    sh[t] = c;
    __syncthreads();
#pragma unroll
    for (int o = 1; o < 512; o <<= 1) {
        int v = (t >= o) ? sh[t - o] : 0;
        __syncthreads();
        sh[t] += v;
        __syncthreads();
    }
    if (t < SCAN_CHUNK) {
        g_rowptr[i] = g_boff[b] + sh[t] - c;    // exclusive
        g_cnt[i] = 0;
        g_dinv[i] = rsqrtf((float)(c + 1));     // deg = in-degree + self loop
    }
}

__global__ void csr_fill_kernel(const int* __restrict__ ei) {
    int e = blockIdx.x * blockDim.x + threadIdx.x;
    if (e >= EE) return;
    int src = ei[e];
    int dst = ei[EE + e];
    int pos = g_rowptr[dst] + atomicAdd(&g_cnt[dst], 1);
    g_csr_src[pos] = src;
}

// ---------------- tf32 tensor-core GEMM v4 ------------------------------------
__device__ __forceinline__ void mma_tf32(float* c, const unsigned* a, const unsigned* b) {
    asm volatile(
        "mma.sync.aligned.m16n8k8.row.col.f32.tf32.tf32.f32 "
        "{%0,%1,%2,%3}, {%4,%5,%6,%7}, {%8,%9}, {%0,%1,%2,%3};"
        : "+f"(c[0]), "+f"(c[1]), "+f"(c[2]), "+f"(c[3])
        : "r"(a[0]), "r"(a[1]), "r"(a[2]), "r"(a[3]), "r"(b[0]), "r"(b[1]));
}

__device__ __forceinline__ void cp_async16(float* sdst, const float* gsrc, bool valid) {
    unsigned saddr = (unsigned)__cvta_generic_to_shared(sdst);
    int sz = valid ? 16 : 0;
    asm volatile("cp.async.ca.shared.global [%0], [%1], 16, %2;"
                 :: "r"(saddr), "l"(gsrc), "r"(sz));
}
__device__ __forceinline__ void cp_commit() { asm volatile("cp.async.commit_group;"); }
template <int N> __device__ __forceinline__ void cp_wait() {
    asm volatile("cp.async.wait_group %0;" :: "n"(N));
}

// C[M,NCOLS] = A[M,K] @ W[K,NCOLS] (+bias)(+relu)(*dinv[row]) -> fp32 / tf32 / half2
// BM=128, BK=16. WM x WN warps; warp tile (128/WM) x (NCOLS/WN).
#define ASTRIDE 20
template <int K, int NCOLS, int WM, int WN,
          bool ACVT, bool RELU, bool BIAS, bool SCALE, int OUTMODE>  // 0=f32,1=tf32,2=half2
__device__ __forceinline__ void gemm_tf32_body(const float* __restrict__ A,
                                               const float* __restrict__ W,
                                               const float* __restrict__ bias,
                                               void* __restrict__ Cv) {
    constexpr int THREADS = WM * WN * 32;
    constexpr int MT = 128 / (16 * WM);
    constexpr int NT = NCOLS / (8 * WN);
    constexpr int BSTRIDE = NCOLS + 8;
    constexpr int NK = K / 16;

    __shared__ float As[2][128 * ASTRIDE];
    __shared__ float Bs[2][16 * BSTRIDE];

    const int tid = threadIdx.x;
    const int wid = tid >> 5, lane = tid & 31;
    const int wm = wid % WM, wn = wid / WM;
    const int g = lane >> 2, t = lane & 3;
    const int m0 = blockIdx.x * 128;

    float acc[MT][NT][4];
#pragma unroll
    for (int mt = 0; mt < MT; mt++)
#pragma unroll
        for (int nt = 0; nt < NT; nt++)
#pragma unroll
            for (int i = 0; i < 4; i++) acc[mt][nt][i] = 0.0f;

    auto load_tiles = [&](int s, int k0) {
#pragma unroll
        for (int idx = tid; idx < 512; idx += THREADS) {   // A: 128x16 = 512 float4
            int r = idx >> 2, c4 = (idx & 3) * 4;
            int gr = m0 + r;
            bool v = (gr < NN);
            const float* src = A + (size_t)(v ? gr : 0) * K + k0 + c4;
            cp_async16(&As[s][r * ASTRIDE + c4], src, v);
        }
#pragma unroll
        for (int idx = tid; idx < 4 * NCOLS; idx += THREADS) {  // B: 16xNCOLS
            int kr = idx / (NCOLS / 4), c4 = (idx % (NCOLS / 4)) * 4;
            cp_async16(&Bs[s][kr * BSTRIDE + c4], W + (size_t)(k0 + kr) * NCOLS + c4, true);
        }
        cp_commit();
    };

    load_tiles(0, 0);
    for (int it = 0; it < NK; it++) {
        int s = it & 1;
        if (it + 1 < NK) {
            load_tiles(s ^ 1, (it + 1) * 16);
            cp_wait<1>();
        } else {
            cp_wait<0>();
        }
        __syncthreads();

#pragma unroll
        for (int ks = 0; ks < 2; ks++) {
            unsigned a[MT][4], bf[NT][2];
#pragma unroll
            for (int mt = 0; mt < MT; mt++) {
                int r = wm * (16 * MT) + mt * 16 + g;
                int c = ks * 8 + t;
                float a0 = As[s][r * ASTRIDE + c];
                float a1 = As[s][(r + 8) * ASTRIDE + c];
                float a2 = As[s][r * ASTRIDE + c + 4];
                float a3 = As[s][(r + 8) * ASTRIDE + c + 4];
                if (ACVT) {
                    a[mt][0] = f2tf32(a0); a[mt][1] = f2tf32(a1);
                    a[mt][2] = f2tf32(a2); a[mt][3] = f2tf32(a3);
                } else {
                    a[mt][0] = __float_as_uint(a0); a[mt][1] = __float_as_uint(a1);
                    a[mt][2] = __float_as_uint(a2); a[mt][3] = __float_as_uint(a3);
                }
            }
#pragma unroll
            for (int nt = 0; nt < NT; nt++) {
                int n = wn * (8 * NT) + nt * 8 + g;
                int k = ks * 8 + t;
                bf[nt][0] = __float_as_uint(Bs[s][k * BSTRIDE + n]);
                bf[nt][1] = __float_as_uint(Bs[s][(k + 4) * BSTRIDE + n]);
            }
#pragma unroll
            for (int mt = 0; mt < MT; mt++)
#pragma unroll
                for (int nt = 0; nt < NT; nt++) mma_tf32(acc[mt][nt], a[mt], bf[nt]);
        }
        __syncthreads();
    }

    // epilogue
#pragma unroll
    for (int mt = 0; mt < MT; mt++) {
        int rbase = m0 + wm * (16 * MT) + mt * 16 + g;
#pragma unroll
        for (int half = 0; half < 2; half++) {
            int r = rbase + half * 8;
            if (r >= NN) continue;
            float sc = SCALE ? g_dinv[r] : 1.0f;
#pragma unroll
            for (int nt = 0; nt < NT; nt++) {
                int col = wn * (8 * NT) + nt * 8 + 2 * t;
                float v0 = acc[mt][nt][half * 2 + 0];
                float v1 = acc[mt][nt][half * 2 + 1];
                if (BIAS) { v0 += bias[col]; v1 += bias[col + 1]; }
                if (RELU) { v0 = fmaxf(v0, 0.0f); v1 = fmaxf(v1, 0.0f); }
                if (SCALE) { v0 *= sc; v1 *= sc; }
                if (OUTMODE == 2) {
                    ((__half2*)Cv)[(size_t)r * (NCOLS / 2) + (col >> 1)] =
                        __floats2half2_rn(v0, v1);
                } else {
                    if (OUTMODE == 1) { v0 = tf32round(v0); v1 = tf32round(v1); }
                    *(float2*)((float*)Cv + (size_t)r * NCOLS + col) = make_float2(v0, v1);
                }
            }
        }
    }
}

// gemm_pre: A = x (raw fp32 -> in-loop cvt), out g_h tf32-rounded
__global__ __launch_bounds__(256, 2) void gemm_pre_kernel(const float* __restrict__ x,
                                                          const float* __restrict__ bp) {
    gemm_tf32_body<DIN, HDIM, 2, 4, true, true, true, false, 1>(x, g_wp_r, bp, g_h);
}

// layer GEMM: A = g_h (pre-rounded), out g_hw2 fp16 (scaled by dinv)
__global__ __launch_bounds__(256, 2) void gemm_layer_kernel(int layer) {
    gemm_tf32_body<HDIM, HDIM, 2, 4, false, false, false, true, 2>(
        g_h, g_wc_r + (size_t)layer * HDIM * HDIM, nullptr, g_hw2);
}

// heads hidden: A = g_h (pre-rounded), B = g_w1cat (pre-rounded), out g_mid fp32
__global__ __launch_bounds__(256, 2) void heads_mid_kernel() {
    gemm_tf32_body<HDIM, MIDC, 2, 4, false, true, true, false, 0>(
        g_h, g_w1cat, g_b1cat, g_mid);
}

// ---------------- fused gather + self + bias + BN + relu + residual ----------
// g_hw2 rows are 64 half2 (256B). lane l owns cols [4l,4l+4) = half2 pair = 8B.
__device__ __forceinline__ void acc_hw(float4& a, const float2* row, int l) {
    float2 raw = row[l];
    __half2 h0 = *(__half2*)&raw.x;
    __half2 h1 = *(__half2*)&raw.y;
    float2 f0 = __half22float2(h0);
    float2 f1 = __half22float2(h1);
    a.x += f0.x; a.y += f0.y; a.z += f1.x; a.w += f1.y;
}

__global__ void gather_kernel(const float* __restrict__ bc_i,
                              const float* __restrict__ rmean,
                              const float* __restrict__ rvar,
                              const float* __restrict__ gamma,
                              const float* __restrict__ beta,
                              int residual) {
    int warp = (blockIdx.x * blockDim.x + threadIdx.x) >> 5;
    int l = threadIdx.x & 31;
    if (warp >= NN) return;
    const int n = warp;
    const int c0 = l * 4;

    const float2* hw = (const float2*)g_hw2;   // 32 float2 per row
    float4 acc0 = make_float4(0.f, 0.f, 0.f, 0.f);
    float4 acc1 = make_float4(0.f, 0.f, 0.f, 0.f);
    acc_hw(acc0, hw + (size_t)n * 32, l);      // self term (pre-scaled by dinv[n])

    int j = g_rowptr[n];
    const int end = g_rowptr[n + 1];
    for (; j + 8 <= end; j += 8) {
        int s0 = __ldg(&g_csr_src[j + 0]);
        int s1 = __ldg(&g_csr_src[j + 1]);
        int s2 = __ldg(&g_csr_src[j + 2]);
        int s3 = __ldg(&g_csr_src[j + 3]);
        int s4 = __ldg(&g_csr_src[j + 4]);
        int s5 = __ldg(&g_csr_src[j + 5]);
        int s6 = __ldg(&g_csr_src[j + 6]);
        int s7 = __ldg(&g_csr_src[j + 7]);
        acc_hw(acc0, hw + (size_t)s0 * 32, l);
        acc_hw(acc1, hw + (size_t)s1 * 32, l);
        acc_hw(acc0, hw + (size_t)s2 * 32, l);
        acc_hw(acc1, hw + (size_t)s3 * 32, l);
        acc_hw(acc0, hw + (size_t)s4 * 32, l);
        acc_hw(acc1, hw + (size_t)s5 * 32, l);
        acc_hw(acc0, hw + (size_t)s6 * 32, l);
        acc_hw(acc1, hw + (size_t)s7 * 32, l);
    }
    for (; j < end; j++) {
        int s = __ldg(&g_csr_src[j]);
        acc_hw(acc1, hw + (size_t)s * 32, l);
    }
    float4 acc = make_float4(acc0.x + acc1.x, acc0.y + acc1.y,
                             acc0.z + acc1.z, acc0.w + acc1.w);

    const float dn = g_dinv[n];
    float4 bc4 = *(const float4*)(bc_i + c0);
    float4 rm4 = *(const float4*)(rmean + c0);
    float4 rv4 = *(const float4*)(rvar + c0);
    float4 ga4 = *(const float4*)(gamma + c0);
    float4 be4 = *(const float4*)(beta + c0);

    float4 o;
    o.x = fmaxf((acc.x * dn + bc4.x - rm4.x) * rsqrtf(rv4.x + EPSBN) * ga4.x + be4.x, 0.0f);
    o.y = fmaxf((acc.y * dn + bc4.y - rm4.y) * rsqrtf(rv4.y + EPSBN) * ga4.y + be4.y, 0.0f);
    o.z = fmaxf((acc.z * dn + bc4.z - rm4.z) * rsqrtf(rv4.z + EPSBN) * ga4.z + be4.z, 0.0f);
    o.w = fmaxf((acc.w * dn + bc4.w - rm4.w) * rsqrtf(rv4.w + EPSBN) * ga4.w + be4.w, 0.0f);

    float4* h4 = (float4*)g_h;
    if (residual) {
        float4 hp = h4[(size_t)n * 32 + l];
        o.x += hp.x; o.y += hp.y; o.z += hp.z; o.w += hp.w;
    }
    // tf32-round so downstream GEMMs can consume raw bits (exact rna)
    o.x = tf32round(o.x); o.y = tf32round(o.y);
    o.z = tf32round(o.z); o.w = tf32round(o.w);
    h4[(size_t)n * 32 + l] = o;
}

// ---------------- heads second layer ------------------------------------------
// out layout: [0,N) risk_scores ; [N,5N) risk_logits [N,4] ; [5N,6N) relevance
__global__ void heads_out_kernel(const float* __restrict__ rs_W2, const float* __restrict__ rs_b2,
                                 const float* __restrict__ rl_W2, const float* __restrict__ rl_b2,
                                 const float* __restrict__ rel_W2, const float* __restrict__ rel_b2,
                                 float* __restrict__ out) {
    __shared__ float w_rs[HHALF];
    __shared__ float w_rl[HHALF * NRL];
    __shared__ float w_rel[HHALF];
    __shared__ float bsm[8];   // [0]=rs_b2, [1..4]=rl_b2, [5]=rel_b2

    const int tid = threadIdx.x;
    if (tid < HHALF) { w_rs[tid] = rs_W2[tid]; w_rel[tid] = rel_W2[tid]; }
    if (tid < HHALF * NRL) w_rl[tid] = rl_W2[tid];
    if (tid == 0) { bsm[0] = rs_b2[0]; bsm[5] = rel_b2[0]; }
    if (tid < NRL) bsm[1 + tid] = rl_b2[tid];
    __syncthreads();

    const int warp = (blockIdx.x * (blockDim.x >> 5)) + (tid >> 5);
    const int l = tid & 31;
    if (warp >= NN) return;
    const int n = warp;

    const float* m = g_mid + (size_t)n * MIDC;
    float m0 = m[l],        m1 = m[l + 32];
    float m2 = m[l + 64],   m3 = m[l + 96];
    float m4 = m[l + 128],  m5 = m[l + 160];

    float prs = m0 * w_rs[l] + m1 * w_rs[l + 32];
    float prel = m4 * w_rel[l] + m5 * w_rel[l + 32];
    float prl[NRL];
#pragma unroll
    for (int j = 0; j < NRL; j++)
        prl[j] = m2 * w_rl[l * NRL + j] + m3 * w_rl[(l + 32) * NRL + j];

#pragma unroll
    for (int o = 16; o; o >>= 1) {
        prs += __shfl_xor_sync(0xffffffffu, prs, o);
        prel += __shfl_xor_sync(0xffffffffu, prel, o);
#pragma unroll
        for (int j = 0; j < NRL; j++) prl[j] += __shfl_xor_sync(0xffffffffu, prl[j], o);
    }
    if (l == 0) {
        out[n] = 1.0f / (1.0f + expf(-(prs + bsm[0])));
#pragma unroll
        for (int j = 0; j < NRL; j++)
            out[(size_t)NN + (size_t)n * NRL + j] = prl[j] + bsm[1 + j];
        out[(size_t)5 * NN + n] = 1.0f / (1.0f + expf(-(prel + bsm[5])));
    }
}

// ---------------- launch ------------------------------------------------------
extern "C" void kernel_launch(void* const* d_in, const int* in_sizes, int n_in,
                              void* d_out, int out_size) {
    const float* x      = (const float*)d_in[0];
    const int*   ei     = (const int*)  d_in[1];
    const float* Wp     = (const float*)d_in[2];
    const float* bp     = (const float*)d_in[3];
    const float* Wc     = (const float*)d_in[4];
    const float* bc     = (const float*)d_in[5];
    const float* gamma  = (const float*)d_in[6];
    const float* beta   = (const float*)d_in[7];
    const float* rmean  = (const float*)d_in[8];
    const float* rvar   = (const float*)d_in[9];
    const float* rel_W1 = (const float*)d_in[10];
    const float* rel_b1 = (const float*)d_in[11];
    const float* rel_W2 = (const float*)d_in[12];
    const float* rel_b2 = (const float*)d_in[13];
    const float* rs_W1  = (const float*)d_in[14];
    const float* rs_b1  = (const float*)d_in[15];
    const float* rs_W2  = (const float*)d_in[16];
    const float* rs_b2  = (const float*)d_in[17];
    const float* rl_W1  = (const float*)d_in[18];
    const float* rl_b1  = (const float*)d_in[19];
    const float* rl_W2  = (const float*)d_in[20];
    const float* rl_b2  = (const float*)d_in[21];
    float* out = (float*)d_out;

    const int T = 256;
    const int gemm_blocks = (NN + 127) / 128;  // 782

    // launches 1-3: prep; launch 4 = gemm_pre (profiled slot)
    deg_init_kernel<<<(NN + T - 1) / T, T>>>();
    deg_count_kernel<<<(EE + T - 1) / T, T>>>(ei);
    round_weights_kernel<<<(DIN * HDIM + T - 1) / T, T>>>(Wp, Wc);
    gemm_pre_kernel<<<gemm_blocks, 256>>>(x, bp);

    scan_partial_kernel<<<SCAN_NB, 512>>>();
    scan_bsum_kernel<<<1, 256>>>();
    scan_fill_kernel<<<SCAN_NB, 512>>>();
    csr_fill_kernel<<<(EE + T - 1) / T, T>>>(ei);
    w1cat_kernel<<<(HDIM * MIDC + T - 1) / T, T>>>(rs_W1, rs_b1, rl_W1, rl_b1, rel_W1, rel_b1);

    const int gather_blocks = (NN * 32 + T - 1) / T;  // 12500
    for (int i = 0; i < NLAYERS; i++) {
        gemm_layer_kernel<<<gemm_blocks, 256>>>(i);
        gather_kernel<<<gather_blocks, T>>>(bc + (size_t)i * HDIM,
                                            rmean + (size_t)i * HDIM,
                                            rvar + (size_t)i * HDIM,
                                            gamma + (size_t)i * HDIM,
                                            beta + (size_t)i * HDIM,
                                            i > 0 ? 1 : 0);
    }

    heads_mid_kernel<<<gemm_blocks, 256>>>();
    heads_out_kernel<<<(NN * 32 + T - 1) / T, T>>>(rs_W2, rs_b2, rl_W2, rl_b2,
                                                   rel_W2, rel_b2, out);
}

// round 13
// speedup vs baseline: 5.0780x; 1.0623x over previous
#include <cuda_runtime.h>
#include <cuda_fp16.h>
#include <math.h>

#define NN 100000
#define EE 1600000
#define DIN 384
#define HDIM 128
#define HHALF 64
#define NLAYERS 3
#define NRL 4
#define EPSBN 1e-5f

#define SCAN_NB 200
#define SCAN_CHUNK 500

#define MIDC 192   // concatenated heads hidden width

// ---------------- scratch (device globals; no allocation allowed) ------------
__device__ float   g_h[NN * HDIM];       // current node features (tf32-rounded)
__device__ __half2 g_hw2[NN * HDIM / 2]; // (h @ Wc[i]) * dinv[row], fp16
__device__ float   g_mid[NN * MIDC];     // heads hidden
__device__ float   g_w1cat[HDIM * MIDC];
__device__ float   g_b1cat[MIDC];
__device__ float   g_wp_r[DIN * HDIM];            // tf32-rounded Wp
__device__ float   g_wc_r[NLAYERS * HDIM * HDIM]; // tf32-rounded Wc
__device__ float   g_dinv[NN];
__device__ int     g_cnt[NN];
__device__ int     g_rowptr[NN + 1];
__device__ int     g_csr_src[EE];
__device__ int     g_bsum[SCAN_NB];
__device__ int     g_boff[SCAN_NB];

__device__ __forceinline__ unsigned f2tf32(float x) {
    unsigned r;
    asm("cvt.rna.tf32.f32 %0, %1;" : "=r"(r) : "f"(x));
    return r;
}
__device__ __forceinline__ float tf32round(float x) {
    return __uint_as_float(f2tf32(x));
}

// ---------------- weight prep: tf32 pre-rounding -----------------------------
__global__ void round_weights_kernel(const float* __restrict__ Wp,
                                     const float* __restrict__ Wc) {
    int idx = blockIdx.x * blockDim.x + threadIdx.x;
    if (idx >= DIN * HDIM) return;
    g_wp_r[idx] = tf32round(Wp[idx]);
    g_wc_r[idx] = tf32round(Wc[idx]);
}

// ---------------- heads weight concat (tf32-rounded) --------------------------
__global__ void w1cat_kernel(const float* __restrict__ rs_W1, const float* __restrict__ rs_b1,
                             const float* __restrict__ rl_W1, const float* __restrict__ rl_b1,
                             const float* __restrict__ rel_W1, const float* __restrict__ rel_b1) {
    int idx = blockIdx.x * blockDim.x + threadIdx.x;   // [0, 128*192)
    if (idx >= HDIM * MIDC) return;
    int k = idx / MIDC, c = idx % MIDC;
    int head = c >> 6, j = c & 63;
    const float* W1 = (head == 0) ? rs_W1 : (head == 1) ? rl_W1 : rel_W1;
    g_w1cat[idx] = tf32round(W1[k * HHALF + j]);
    if (k == 0) {
        const float* B1 = (head == 0) ? rs_b1 : (head == 1) ? rl_b1 : rel_b1;
        g_b1cat[c] = B1[j];
    }
}

// ---------------- degree count ------------------------------------------------
__global__ void deg_init_kernel() {
    int i = blockIdx.x * blockDim.x + threadIdx.x;
    if (i < NN) g_cnt[i] = 0;
}

__global__ void deg_count_kernel(const int* __restrict__ ei) {
    int e = blockIdx.x * blockDim.x + threadIdx.x;
    if (e < EE) atomicAdd(&g_cnt[ei[EE + e]], 1);
}

// ---------------- 3-phase parallel scan --------------------------------------
__global__ void scan_partial_kernel() {   // grid SCAN_NB, block 512
    __shared__ int sh[512];
    int b = blockIdx.x, t = threadIdx.x;
    int i = b * SCAN_CHUNK + t;
    sh[t] = (t < SCAN_CHUNK) ? g_cnt[i] : 0;
    __syncthreads();
#pragma unroll
    for (int o = 256; o; o >>= 1) {
        if (t < o) sh[t] += sh[t + o];
        __syncthreads();
    }
    if (t == 0) g_bsum[b] = sh[0];
}

__global__ void scan_bsum_kernel() {      // 1 block, 256 threads
    __shared__ int sh[256];
    int t = threadIdx.x;
    sh[t] = (t < SCAN_NB) ? g_bsum[t] : 0;
    __syncthreads();
#pragma unroll
    for (int o = 1; o < 256; o <<= 1) {
        int v = (t >= o) ? sh[t - o] : 0;
        __syncthreads();
        sh[t] += v;
        __syncthreads();
    }
    if (t < SCAN_NB) g_boff[t] = (t ? sh[t - 1] : 0);
    if (t == 0) g_rowptr[NN] = EE;
}

__global__ void scan_fill_kernel() {      // grid SCAN_NB, block 512
    __shared__ int sh[512];
    int b = blockIdx.x, t = threadIdx.x;
    int i = b * SCAN_CHUNK + t;
    int c = (t < SCAN_CHUNK) ? g_cnt[i] : 0;
    sh[t] = c;
    __syncthreads();
#pragma unroll
    for (int o = 1; o < 512; o <<= 1) {
        int v = (t >= o) ? sh[t - o] : 0;
        __syncthreads();
        sh[t] += v;
        __syncthreads();
    }
    if (t < SCAN_CHUNK) {
        g_rowptr[i] = g_boff[b] + sh[t] - c;    // exclusive
        g_cnt[i] = 0;
        g_dinv[i] = rsqrtf((float)(c + 1));     // deg = in-degree + self loop
    }
}

__global__ void csr_fill_kernel(const int* __restrict__ ei) {
    int e = blockIdx.x * blockDim.x + threadIdx.x;
    if (e >= EE) return;
    int src = ei[e];
    int dst = ei[EE + e];
    int pos = g_rowptr[dst] + atomicAdd(&g_cnt[dst], 1);
    g_csr_src[pos] = src;
}

// ---------------- tf32 tensor-core GEMM v5 (multi-stage cp.async) -------------
__device__ __forceinline__ void mma_tf32(float* c, const unsigned* a, const unsigned* b) {
    asm volatile(
        "mma.sync.aligned.m16n8k8.row.col.f32.tf32.tf32.f32 "
        "{%0,%1,%2,%3}, {%4,%5,%6,%7}, {%8,%9}, {%0,%1,%2,%3};"
        : "+f"(c[0]), "+f"(c[1]), "+f"(c[2]), "+f"(c[3])
        : "r"(a[0]), "r"(a[1]), "r"(a[2]), "r"(a[3]), "r"(b[0]), "r"(b[1]));
}

__device__ __forceinline__ void cp_async16(float* sdst, const float* gsrc, bool valid) {
    unsigned saddr = (unsigned)__cvta_generic_to_shared(sdst);
    int sz = valid ? 16 : 0;
    asm volatile("cp.async.cg.shared.global [%0], [%1], 16, %2;"
                 :: "r"(saddr), "l"(gsrc), "r"(sz));
}
__device__ __forceinline__ void cp_commit() { asm volatile("cp.async.commit_group;"); }
template <int N> __device__ __forceinline__ void cp_wait() {
    asm volatile("cp.async.wait_group %0;" :: "n"(N));
}

// C[M,NCOLS] = A[M,K] @ W[K,NCOLS] (+bias)(+relu)(*dinv[row]) -> f32/tf32/half2
// BM=128, BK=16. WM x WN warps; warp tile (128/WM) x (NCOLS/WN). NSTAGE-deep pipeline.
#define ASTRIDE 20
template <int K, int NCOLS, int WM, int WN, int NSTAGE,
          bool ACVT, bool RELU, bool BIAS, bool SCALE, int OUTMODE>  // 0=f32,1=tf32,2=half2
__device__ __forceinline__ void gemm_tf32_body(const float* __restrict__ A,
                                               const float* __restrict__ W,
                                               const float* __restrict__ bias,
                                               void* __restrict__ Cv) {
    constexpr int THREADS = WM * WN * 32;
    constexpr int MT = 128 / (16 * WM);
    constexpr int NT = NCOLS / (8 * WN);
    constexpr int BSTRIDE = NCOLS + 8;
    constexpr int NK = K / 16;
    constexpr int SA = 128 * ASTRIDE;     // floats per A stage
    constexpr int SB = 16 * BSTRIDE;      // floats per B stage
    constexpr int SS = SA + SB;

    extern __shared__ float sm[];

    const int tid = threadIdx.x;
    const int wid = tid >> 5, lane = tid & 31;
    const int wm = wid % WM, wn = wid / WM;
    const int g = lane >> 2, t = lane & 3;
    const int m0 = blockIdx.x * 128;

    float acc[MT][NT][4];
#pragma unroll
    for (int mt = 0; mt < MT; mt++)
#pragma unroll
        for (int nt = 0; nt < NT; nt++)
#pragma unroll
            for (int i = 0; i < 4; i++) acc[mt][nt][i] = 0.0f;

    auto load_tiles = [&](int s, int k0) {
        float* As = sm + s * SS;
        float* Bs = As + SA;
#pragma unroll
        for (int idx = tid; idx < 512; idx += THREADS) {   // A: 128x16 = 512 float4
            int r = idx >> 2, c4 = (idx & 3) * 4;
            int gr = m0 + r;
            bool v = (gr < NN);
            const float* src = A + (size_t)(v ? gr : 0) * K + k0 + c4;
            cp_async16(&As[r * ASTRIDE + c4], src, v);
        }
#pragma unroll
        for (int idx = tid; idx < 4 * NCOLS; idx += THREADS) {  // B: 16xNCOLS
            int kr = idx / (NCOLS / 4), c4 = (idx % (NCOLS / 4)) * 4;
            cp_async16(&Bs[kr * BSTRIDE + c4], W + (size_t)(k0 + kr) * NCOLS + c4, true);
        }
        cp_commit();
    };

#pragma unroll
    for (int p = 0; p < NSTAGE - 1; p++) load_tiles(p, p * 16);

    for (int it = 0; it < NK; it++) {
        int s = it % NSTAGE;
        int pf = it + NSTAGE - 1;
        if (pf < NK) load_tiles(pf % NSTAGE, pf * 16);
        else cp_commit();                 // keep group count uniform
        cp_wait<NSTAGE - 1>();            // stage `it` ready
        __syncthreads();

        const float* As = sm + s * SS;
        const float* Bs = As + SA;
#pragma unroll
        for (int ks = 0; ks < 2; ks++) {
            unsigned a[MT][4], bf[NT][2];
#pragma unroll
            for (int mt = 0; mt < MT; mt++) {
                int r = wm * (16 * MT) + mt * 16 + g;
                int c = ks * 8 + t;
                float a0 = As[r * ASTRIDE + c];
                float a1 = As[(r + 8) * ASTRIDE + c];
                float a2 = As[r * ASTRIDE + c + 4];
                float a3 = As[(r + 8) * ASTRIDE + c + 4];
                if (ACVT) {
                    a[mt][0] = f2tf32(a0); a[mt][1] = f2tf32(a1);
                    a[mt][2] = f2tf32(a2); a[mt][3] = f2tf32(a3);
                } else {
                    a[mt][0] = __float_as_uint(a0); a[mt][1] = __float_as_uint(a1);
                    a[mt][2] = __float_as_uint(a2); a[mt][3] = __float_as_uint(a3);
                }
            }
#pragma unroll
            for (int nt = 0; nt < NT; nt++) {
                int n = wn * (8 * NT) + nt * 8 + g;
                int k = ks * 8 + t;
                bf[nt][0] = __float_as_uint(Bs[k * BSTRIDE + n]);
                bf[nt][1] = __float_as_uint(Bs[(k + 4) * BSTRIDE + n]);
            }
#pragma unroll
            for (int mt = 0; mt < MT; mt++)
#pragma unroll
                for (int nt = 0; nt < NT; nt++) mma_tf32(acc[mt][nt], a[mt], bf[nt]);
        }
        __syncthreads();
    }

    // epilogue
#pragma unroll
    for (int mt = 0; mt < MT; mt++) {
        int rbase = m0 + wm * (16 * MT) + mt * 16 + g;
#pragma unroll
        for (int half = 0; half < 2; half++) {
            int r = rbase + half * 8;
            if (r >= NN) continue;
            float sc = SCALE ? g_dinv[r] : 1.0f;
#pragma unroll
            for (int nt = 0; nt < NT; nt++) {
                int col = wn * (8 * NT) + nt * 8 + 2 * t;
                float v0 = acc[mt][nt][half * 2 + 0];
                float v1 = acc[mt][nt][half * 2 + 1];
                if (BIAS) { v0 += bias[col]; v1 += bias[col + 1]; }
                if (RELU) { v0 = fmaxf(v0, 0.0f); v1 = fmaxf(v1, 0.0f); }
                if (SCALE) { v0 *= sc; v1 *= sc; }
                if (OUTMODE == 2) {
                    ((__half2*)Cv)[(size_t)r * (NCOLS / 2) + (col >> 1)] =
                        __floats2half2_rn(v0, v1);
                } else {
                    if (OUTMODE == 1) { v0 = tf32round(v0); v1 = tf32round(v1); }
                    *(float2*)((float*)Cv + (size_t)r * NCOLS + col) = make_float2(v0, v1);
                }
            }
        }
    }
}

// dynamic smem sizes (bytes)
#define SMEM_PRE   (4 * (128 * ASTRIDE + 16 * (HDIM + 8)) * 4)   // 75776
#define SMEM_LAYER (3 * (128 * ASTRIDE + 16 * (HDIM + 8)) * 4)   // 56832
#define SMEM_MID   (3 * (128 * ASTRIDE + 16 * (MIDC + 8)) * 4)   // 69120

// gemm_pre: A = x (raw fp32 -> in-loop cvt), out g_h tf32-rounded. 128 thr, 4 stages.
__global__ __launch_bounds__(128) void gemm_pre_kernel(const float* __restrict__ x,
                                                       const float* __restrict__ bp) {
    gemm_tf32_body<DIN, HDIM, 2, 2, 4, true, true, true, false, 1>(x, g_wp_r, bp, g_h);
}

// layer GEMM: A = g_h (pre-rounded), out g_hw2 fp16 (scaled by dinv). 128 thr, 3 stages.
__global__ __launch_bounds__(128) void gemm_layer_kernel(int layer) {
    gemm_tf32_body<HDIM, HDIM, 2, 2, 3, false, false, false, true, 2>(
        g_h, g_wc_r + (size_t)layer * HDIM * HDIM, nullptr, g_hw2);
}

// heads hidden: A = g_h, B = g_w1cat, out g_mid fp32. 256 thr, 3 stages.
__global__ __launch_bounds__(256) void heads_mid_kernel() {
    gemm_tf32_body<HDIM, MIDC, 2, 4, 3, false, true, true, false, 0>(
        g_h, g_w1cat, g_b1cat, g_mid);
}

// ---------------- fused gather + self + bias + BN + relu + residual ----------
__device__ __forceinline__ void acc_hw(float4& a, const float2* row, int l) {
    float2 raw = row[l];
    __half2 h0 = *(__half2*)&raw.x;
    __half2 h1 = *(__half2*)&raw.y;
    float2 f0 = __half22float2(h0);
    float2 f1 = __half22float2(h1);
    a.x += f0.x; a.y += f0.y; a.z += f1.x; a.w += f1.y;
}

__global__ void gather_kernel(const float* __restrict__ bc_i,
                              const float* __restrict__ rmean,
                              const float* __restrict__ rvar,
                              const float* __restrict__ gamma,
                              const float* __restrict__ beta,
                              int residual) {
    int warp = (blockIdx.x * blockDim.x + threadIdx.x) >> 5;
    int l = threadIdx.x & 31;
    if (warp >= NN) return;
    const int n = warp;
    const int c0 = l * 4;

    const float2* hw = (const float2*)g_hw2;   // 32 float2 per row
    float4 acc0 = make_float4(0.f, 0.f, 0.f, 0.f);
    float4 acc1 = make_float4(0.f, 0.f, 0.f, 0.f);
    acc_hw(acc0, hw + (size_t)n * 32, l);      // self term (pre-scaled by dinv[n])

    int j = g_rowptr[n];
    const int end = g_rowptr[n + 1];
    for (; j + 8 <= end; j += 8) {
        int s0 = __ldg(&g_csr_src[j + 0]);
        int s1 = __ldg(&g_csr_src[j + 1]);
        int s2 = __ldg(&g_csr_src[j + 2]);
        int s3 = __ldg(&g_csr_src[j + 3]);
        int s4 = __ldg(&g_csr_src[j + 4]);
        int s5 = __ldg(&g_csr_src[j + 5]);
        int s6 = __ldg(&g_csr_src[j + 6]);
        int s7 = __ldg(&g_csr_src[j + 7]);
        acc_hw(acc0, hw + (size_t)s0 * 32, l);
        acc_hw(acc1, hw + (size_t)s1 * 32, l);
        acc_hw(acc0, hw + (size_t)s2 * 32, l);
        acc_hw(acc1, hw + (size_t)s3 * 32, l);
        acc_hw(acc0, hw + (size_t)s4 * 32, l);
        acc_hw(acc1, hw + (size_t)s5 * 32, l);
        acc_hw(acc0, hw + (size_t)s6 * 32, l);
        acc_hw(acc1, hw + (size_t)s7 * 32, l);
    }
    for (; j < end; j++) {
        int s = __ldg(&g_csr_src[j]);
        acc_hw(acc1, hw + (size_t)s * 32, l);
    }
    float4 acc = make_float4(acc0.x + acc1.x, acc0.y + acc1.y,
                             acc0.z + acc1.z, acc0.w + acc1.w);

    const float dn = g_dinv[n];
    float4 bc4 = *(const float4*)(bc_i + c0);
    float4 rm4 = *(const float4*)(rmean + c0);
    float4 rv4 = *(const float4*)(rvar + c0);
    float4 ga4 = *(const float4*)(gamma + c0);
    float4 be4 = *(const float4*)(beta + c0);

    float4 o;
    o.x = fmaxf((acc.x * dn + bc4.x - rm4.x) * rsqrtf(rv4.x + EPSBN) * ga4.x + be4.x, 0.0f);
    o.y = fmaxf((acc.y * dn + bc4.y - rm4.y) * rsqrtf(rv4.y + EPSBN) * ga4.y + be4.y, 0.0f);
    o.z = fmaxf((acc.z * dn + bc4.z - rm4.z) * rsqrtf(rv4.z + EPSBN) * ga4.z + be4.z, 0.0f);
    o.w = fmaxf((acc.w * dn + bc4.w - rm4.w) * rsqrtf(rv4.w + EPSBN) * ga4.w + be4.w, 0.0f);

    float4* h4 = (float4*)g_h;
    if (residual) {
        float4 hp = h4[(size_t)n * 32 + l];
        o.x += hp.x; o.y += hp.y; o.z += hp.z; o.w += hp.w;
    }
    // tf32-round so downstream GEMMs can consume raw bits (exact rna)
    o.x = tf32round(o.x); o.y = tf32round(o.y);
    o.z = tf32round(o.z); o.w = tf32round(o.w);
    h4[(size_t)n * 32 + l] = o;
}

// ---------------- heads second layer ------------------------------------------
// out layout: [0,N) risk_scores ; [N,5N) risk_logits [N,4] ; [5N,6N) relevance
__global__ void heads_out_kernel(const float* __restrict__ rs_W2, const float* __restrict__ rs_b2,
                                 const float* __restrict__ rl_W2, const float* __restrict__ rl_b2,
                                 const float* __restrict__ rel_W2, const float* __restrict__ rel_b2,
                                 float* __restrict__ out) {
    __shared__ float w_rs[HHALF];
    __shared__ float w_rl[HHALF * NRL];
    __shared__ float w_rel[HHALF];
    __shared__ float bsm[8];   // [0]=rs_b2, [1..4]=rl_b2, [5]=rel_b2

    const int tid = threadIdx.x;
    if (tid < HHALF) { w_rs[tid] = rs_W2[tid]; w_rel[tid] = rel_W2[tid]; }
    if (tid < HHALF * NRL) w_rl[tid] = rl_W2[tid];
    if (tid == 0) { bsm[0] = rs_b2[0]; bsm[5] = rel_b2[0]; }
    if (tid < NRL) bsm[1 + tid] = rl_b2[tid];
    __syncthreads();

    const int warp = (blockIdx.x * (blockDim.x >> 5)) + (tid >> 5);
    const int l = tid & 31;
    if (warp >= NN) return;
    const int n = warp;

    const float* m = g_mid + (size_t)n * MIDC;
    float m0 = m[l],        m1 = m[l + 32];
    float m2 = m[l + 64],   m3 = m[l + 96];
    float m4 = m[l + 128],  m5 = m[l + 160];

    float prs = m0 * w_rs[l] + m1 * w_rs[l + 32];
    float prel = m4 * w_rel[l] + m5 * w_rel[l + 32];
    float prl[NRL];
#pragma unroll
    for (int j = 0; j < NRL; j++)
        prl[j] = m2 * w_rl[l * NRL + j] + m3 * w_rl[(l + 32) * NRL + j];

#pragma unroll
    for (int o = 16; o; o >>= 1) {
        prs += __shfl_xor_sync(0xffffffffu, prs, o);
        prel += __shfl_xor_sync(0xffffffffu, prel, o);
#pragma unroll
        for (int j = 0; j < NRL; j++) prl[j] += __shfl_xor_sync(0xffffffffu, prl[j], o);
    }
    if (l == 0) {
        out[n] = 1.0f / (1.0f + expf(-(prs + bsm[0])));
#pragma unroll
        for (int j = 0; j < NRL; j++)
            out[(size_t)NN + (size_t)n * NRL + j] = prl[j] + bsm[1 + j];
        out[(size_t)5 * NN + n] = 1.0f / (1.0f + expf(-(prel + bsm[5])));
    }
}

// ---------------- launch ------------------------------------------------------
extern "C" void kernel_launch(void* const* d_in, const int* in_sizes, int n_in,
                              void* d_out, int out_size) {
    const float* x      = (const float*)d_in[0];
    const int*   ei     = (const int*)  d_in[1];
    const float* Wp     = (const float*)d_in[2];
    const float* bp     = (const float*)d_in[3];
    const float* Wc     = (const float*)d_in[4];
    const float* bc     = (const float*)d_in[5];
    const float* gamma  = (const float*)d_in[6];
    const float* beta   = (const float*)d_in[7];
    const float* rmean  = (const float*)d_in[8];
    const float* rvar   = (const float*)d_in[9];
    const float* rel_W1 = (const float*)d_in[10];
    const float* rel_b1 = (const float*)d_in[11];
    const float* rel_W2 = (const float*)d_in[12];
    const float* rel_b2 = (const float*)d_in[13];
    const float* rs_W1  = (const float*)d_in[14];
    const float* rs_b1  = (const float*)d_in[15];
    const float* rs_W2  = (const float*)d_in[16];
    const float* rs_b2  = (const float*)d_in[17];
    const float* rl_W1  = (const float*)d_in[18];
    const float* rl_b1  = (const float*)d_in[19];
    const float* rl_W2  = (const float*)d_in[20];
    const float* rl_b2  = (const float*)d_in[21];
    float* out = (float*)d_out;

    // raise dynamic smem limits (idempotent, capture-safe host calls)
    cudaFuncSetAttribute(gemm_pre_kernel, cudaFuncAttributeMaxDynamicSharedMemorySize, SMEM_PRE);
    cudaFuncSetAttribute(gemm_layer_kernel, cudaFuncAttributeMaxDynamicSharedMemorySize, SMEM_LAYER);
    cudaFuncSetAttribute(heads_mid_kernel, cudaFuncAttributeMaxDynamicSharedMemorySize, SMEM_MID);

    const int T = 256;
    const int gemm_blocks = (NN + 127) / 128;  // 782

    // launches 1-3: prep; launch 4 = gemm_pre (profiled slot)
    deg_init_kernel<<<(NN + T - 1) / T, T>>>();
    deg_count_kernel<<<(EE + T - 1) / T, T>>>(ei);
    round_weights_kernel<<<(DIN * HDIM + T - 1) / T, T>>>(Wp, Wc);
    gemm_pre_kernel<<<gemm_blocks, 128, SMEM_PRE>>>(x, bp);

    scan_partial_kernel<<<SCAN_NB, 512>>>();
    scan_bsum_kernel<<<1, 256>>>();
    scan_fill_kernel<<<SCAN_NB, 512>>>();
    csr_fill_kernel<<<(EE + T - 1) / T, T>>>(ei);
    w1cat_kernel<<<(HDIM * MIDC + T - 1) / T, T>>>(rs_W1, rs_b1, rl_W1, rl_b1, rel_W1, rel_b1);

    const int gather_blocks = (NN * 32 + T - 1) / T;  // 12500
    for (int i = 0; i < NLAYERS; i++) {
        gemm_layer_kernel<<<gemm_blocks, 128, SMEM_LAYER>>>(i);
        gather_kernel<<<gather_blocks, T>>>(bc + (size_t)i * HDIM,
                                            rmean + (size_t)i * HDIM,
                                            rvar + (size_t)i * HDIM,
                                            gamma + (size_t)i * HDIM,
                                            beta + (size_t)i * HDIM,
                                            i > 0 ? 1 : 0);
    }

    heads_mid_kernel<<<gemm_blocks, 256, SMEM_MID>>>();
    heads_out_kernel<<<(NN * 32 + T - 1) / T, T>>>(rs_W2, rs_b2, rl_W2, rl_b2,
                                                   rel_W2, rel_b2, out);
}